// round 6
// baseline (speedup 1.0000x reference)
#include <cuda_runtime.h>
#include <mma.h>
#include <math.h>

using namespace nvcuda;

#define EN 131072
#define NN 8192
#define WFULL 0xffffffffu

__device__ float4 g_y4[EN];
__device__ float g_emb[EN * 10];
__device__ float g_state[NN * 256];
__device__ float g_state2[NN * 256];
__device__ float g_A[NN * 256];
__device__ float g_w[(size_t)EN * 320];
__device__ int   g_deg[NN];
__device__ int   g_cursor[NN];
__device__ int   g_rowstart[NN + 1];
__device__ int   g_csr[EN];
__device__ int   g_csrc[EN];

#define IS32 0.17677669529663687f
#define IS10 0.31622776601683794f
#define IV2  0.7071067811865476f
#define IV3  0.5773502691896258f
#define CSC  0.3826834323650898f
#define CXC  0.9238795325112867f
#define CS32 (CSC * IS32)
#define CX8  (CXC * 0.125f)
#define CX96 (CXC * 0.10206207261596575f)
#define EMBSC 2.8234622306428f
#define OUTSC 0.044194173824159216f

__device__ __forceinline__ float to_tf32(float x) {
    float r;
    asm("cvt.rna.tf32.f32 %0, %1;" : "=f"(r) : "f"(x));
    return r;
}

// -------- k_setup: edge geometry + degree hist (blocks 0..511)
//          and layer-0 lin1 reading x directly (blocks 512..1535)
__global__ void __launch_bounds__(256) k_setup(
    const float* __restrict__ x, const float* __restrict__ ev,
    const int* __restrict__ dst,
    const float* __restrict__ w1so, const float* __restrict__ w1se,
    const float* __restrict__ w1vo, const float* __restrict__ w1ve) {
    __shared__ float ws[4096];
    int b = blockIdx.x, t = threadIdx.x;
    if (b < 512) {
        int e = b * 256 + t;
        float vx = ev[e*3], vy = ev[e*3+1], vz = ev[e*3+2];
        float r = sqrtf(vx*vx + vy*vy + vz*vz);
        float inv = 1.0f / (r + 1e-12f);
        float uu = 0.5f * r - 2.0f;
        float cut;
        if (uu > 0.0f) cut = 0.0f;
        else if (uu < -1.0f) cut = 1.0f;
        else cut = 0.5f * (1.0f - cosf(3.14159265358979323846f * uu));
        const float SQ3 = 1.7320508075688772f;
        float s = SQ3 * inv * cut;
        g_y4[e] = make_float4(cut, s*vx, s*vy, s*vz);
#pragma unroll
        for (int i = 0; i < 10; i++) {
            float d = (r - (4.0f/9.0f)*(float)i) * 2.25f;
            g_emb[e*10+i] = expf(-d*d) * EMBSC;
        }
        atomicAdd(&g_deg[dst[e]], 1);
        return;
    }
    // lin1 layer 0
    for (int i = t; i < 1024; i += 256) {
        ws[i] = w1so[i]; ws[1024+i] = w1se[i]; ws[2048+i] = w1vo[i]; ws[3072+i] = w1ve[i];
    }
    __syncthreads();
    int u = t & 31, wp = t >> 5;
    int n = (b - 512) * 8 + wp;
    const float* s = x + n * 256;
    float so = s[u], se = s[32+u];
    float vo0 = s[64+u*3], vo1 = s[64+u*3+1], vo2 = s[64+u*3+2];
    float ve0 = s[160+u*3], ve1 = s[160+u*3+1], ve2 = s[160+u*3+2];
    float aso=0, ase=0, avo0=0, avo1=0, avo2=0, ave0=0, ave1=0, ave2=0;
#pragma unroll
    for (int v = 0; v < 32; v++) {
        float a = __shfl_sync(WFULL, so, v), bb = __shfl_sync(WFULL, se, v);
        float c0 = __shfl_sync(WFULL, vo0, v), c1 = __shfl_sync(WFULL, vo1, v), c2 = __shfl_sync(WFULL, vo2, v);
        float d0 = __shfl_sync(WFULL, ve0, v), d1 = __shfl_sync(WFULL, ve1, v), d2 = __shfl_sync(WFULL, ve2, v);
        float w0 = ws[v*32+u], w1 = ws[1024+v*32+u], w2 = ws[2048+v*32+u], w3 = ws[3072+v*32+u];
        aso += a*w0; ase += bb*w1;
        avo0 += c0*w2; avo1 += c1*w2; avo2 += c2*w2;
        ave0 += d0*w3; ave1 += d1*w3; ave2 += d2*w3;
    }
    float* A = g_A + n * 256;
    A[u] = aso*IS32; A[32+u] = ase*IS32;
    A[64+u] = avo0*IS32; A[96+u] = avo1*IS32; A[128+u] = avo2*IS32;
    A[160+u] = ave0*IS32; A[192+u] = ave1*IS32; A[224+u] = ave2*IS32;
}

__global__ void k_scan(float* __restrict__ out) {
    __shared__ int part[1024];
    int t = threadIdx.x;
    if (t < 16) out[t] = 0.0f;
    int loc[8]; int run = 0;
#pragma unroll
    for (int i = 0; i < 8; i++) { loc[i] = run; run += g_deg[t*8+i]; }
    part[t] = run;
    __syncthreads();
    for (int off = 1; off < 1024; off <<= 1) {
        int xv = (t >= off) ? part[t-off] : 0;
        __syncthreads();
        part[t] += xv;
        __syncthreads();
    }
    int base = (t > 0) ? part[t-1] : 0;
#pragma unroll
    for (int i = 0; i < 8; i++) g_rowstart[t*8+i] = base + loc[i];
    if (t == 1023) g_rowstart[NN] = EN;
}

__global__ void k_scatter(const int* __restrict__ dst, const int* __restrict__ src) {
    int e = blockIdx.x * blockDim.x + threadIdx.x;
    if (e >= EN) return;
    int d = dst[e];
    int pos = atomicAdd(&g_cursor[d], 1);
    int slot = g_rowstart[d] + pos;
    g_csr[slot] = e;
    g_csrc[slot] = src[e];
}

// node linear-1 for layers 1,2
__global__ void __launch_bounds__(256) k_lin1(
    const float* __restrict__ w1so, const float* __restrict__ w1se,
    const float* __restrict__ w1vo, const float* __restrict__ w1ve,
    const float* __restrict__ stin_base) {
    __shared__ float ws[4096];
    int t = threadIdx.x;
    for (int i = t; i < 1024; i += 256) {
        ws[i] = w1so[i]; ws[1024+i] = w1se[i]; ws[2048+i] = w1vo[i]; ws[3072+i] = w1ve[i];
    }
    __syncthreads();
    int u = t & 31, wp = t >> 5;
    int n = blockIdx.x * 8 + wp;
    const float* s = stin_base + n * 256;
    float so = s[u], se = s[32+u];
    float vo0 = s[64+u*3], vo1 = s[64+u*3+1], vo2 = s[64+u*3+2];
    float ve0 = s[160+u*3], ve1 = s[160+u*3+1], ve2 = s[160+u*3+2];
    float aso=0, ase=0, avo0=0, avo1=0, avo2=0, ave0=0, ave1=0, ave2=0;
#pragma unroll
    for (int v = 0; v < 32; v++) {
        float a = __shfl_sync(WFULL, so, v), b = __shfl_sync(WFULL, se, v);
        float c0 = __shfl_sync(WFULL, vo0, v), c1 = __shfl_sync(WFULL, vo1, v), c2 = __shfl_sync(WFULL, vo2, v);
        float d0 = __shfl_sync(WFULL, ve0, v), d1 = __shfl_sync(WFULL, ve1, v), d2 = __shfl_sync(WFULL, ve2, v);
        float w0 = ws[v*32+u], w1 = ws[1024+v*32+u], w2 = ws[2048+v*32+u], w3 = ws[3072+v*32+u];
        aso += a*w0; ase += b*w1;
        avo0 += c0*w2; avo1 += c1*w2; avo2 += c2*w2;
        ave0 += d0*w3; ave1 += d1*w3; ave2 += d2*w3;
    }
    float* A = g_A + n * 256;
    A[u] = aso*IS32; A[32+u] = ase*IS32;
    A[64+u] = avo0*IS32; A[96+u] = avo1*IS32; A[128+u] = avo2*IS32;
    A[160+u] = ave0*IS32; A[192+u] = ave1*IS32; A[224+u] = ave2*IS32;
}

// ---------------- radial MLP via tf32 tensor cores ----------------
// Block: 128 edges x 320 outputs, 640 threads = 20 warps as 4M x 5N.
// Warp tile: 32 rows x 64 cols (2 A frags x 4 B frags, c = 64 regs).
// LDB = 336 (== 16 mod 32): consecutive B rows tile the 32 banks -> conflict-free.
#define LDH 104
#define LDB 336
#define SM_H 0
#define SM_B (128 * LDH)
#define SM_RW1 (SM_B + 104 * LDB)
#define SM_EMB (SM_RW1 + 1000)
#define SM_RAD_FLOATS (SM_EMB + 1280)

__global__ void __launch_bounds__(640) k_radial_tc(
    const float* __restrict__ rw1, const float* __restrict__ rw2) {
    extern __shared__ float sh[];
    float* h_s   = sh + SM_H;
    float* B_s   = sh + SM_B;
    float* rw1_s = sh + SM_RW1;
    float* emb_s = sh + SM_EMB;
    int t = threadIdx.x;
    int e0 = blockIdx.x * 128;

    for (int i = t; i < 1000; i += 640) rw1_s[i] = rw1[i];
    for (int i = t; i < 1280; i += 640) emb_s[i] = g_emb[e0*10 + i];
    for (int i = t; i < 104*320; i += 640) {
        int k = i / 320, n = i - k*320;
        B_s[k*LDB + n] = (k < 100) ? to_tf32(rw2[k*320 + n]) : 0.0f;
    }
    __syncthreads();
    for (int i = t; i < 12800; i += 640) {
        int e = i / 100, j = i - e*100;
        float s = 0.0f;
#pragma unroll
        for (int k = 0; k < 10; k++) s += emb_s[e*10+k] * rw1_s[k*100+j];
        s *= IS10;
        h_s[e*LDH + j] = to_tf32(s / (1.0f + __expf(-s)));
    }
    if (t < 512) {
        int e = t >> 2, c = t & 3;
        h_s[e*LDH + 100 + c] = 0.0f;
    }
    __syncthreads();

    int w = t >> 5;
    int mg = w / 5;    // 0..3 -> rows [mg*32, +32)
    int ng = w % 5;    // 0..4 -> cols [ng*64, +64)

    wmma::fragment<wmma::accumulator, 16, 16, 8, float> c[2][4];
#pragma unroll
    for (int mi = 0; mi < 2; mi++)
#pragma unroll
        for (int ni = 0; ni < 4; ni++) wmma::fill_fragment(c[mi][ni], 0.0f);

    for (int kt = 0; kt < 13; kt++) {
        wmma::fragment<wmma::matrix_a, 16, 16, 8, wmma::precision::tf32, wmma::row_major> a[2];
#pragma unroll
        for (int mi = 0; mi < 2; mi++)
            wmma::load_matrix_sync(a[mi], h_s + (mg*32 + mi*16)*LDH + kt*8, LDH);
#pragma unroll
        for (int ni = 0; ni < 4; ni++) {
            wmma::fragment<wmma::matrix_b, 16, 16, 8, wmma::precision::tf32, wmma::row_major> b;
            wmma::load_matrix_sync(b, B_s + (kt*8)*LDB + ng*64 + ni*16, LDB);
            wmma::mma_sync(c[0][ni], a[0], b, c[0][ni]);
            wmma::mma_sync(c[1][ni], a[1], b, c[1][ni]);
        }
    }
#pragma unroll
    for (int mi = 0; mi < 2; mi++)
#pragma unroll
        for (int ni = 0; ni < 4; ni++) {
#pragma unroll
            for (int i = 0; i < c[mi][ni].num_elements; i++) c[mi][ni].x[i] *= 0.1f;
            wmma::store_matrix_sync(
                g_w + (size_t)(e0 + mg*32 + mi*16) * 320 + ng*64 + ni*16,
                c[mi][ni], 320, wmma::mem_row_major);
        }
}

// dst-centric messages + fused node update (warp per node)
__global__ void __launch_bounds__(256) k_msg(
    const float* __restrict__ wsso, const float* __restrict__ wsse,
    const float* __restrict__ wsvo, const float* __restrict__ wsve,
    const float* __restrict__ w2so, const float* __restrict__ w2se,
    const float* __restrict__ w2vo, const float* __restrict__ w2ve,
    const float* __restrict__ stin_base, float* __restrict__ stout_base) {
    extern __shared__ float sm[];
    float* s_wsso = sm;
    float* s_wsse = sm + 1024;
    float* s_wsvo = sm + 4096;
    float* s_wsve = sm + 5120;
    float* s_w2so = sm + 6144;
    float* s_w2se = sm + 8192;
    float* s_w2vo = sm + 14336;
    float* s_w2ve = sm + 17408;
    int t = threadIdx.x;
    for (int i = t; i < 1024; i += 256) { s_wsso[i]=wsso[i]; s_wsvo[i]=wsvo[i]; s_wsve[i]=wsve[i]; }
    for (int i = t; i < 3072; i += 256) { s_wsse[i]=wsse[i]; s_w2vo[i]=w2vo[i]; s_w2ve[i]=w2ve[i]; }
    for (int i = t; i < 2048; i += 256) s_w2so[i]=w2so[i];
    for (int i = t; i < 6144; i += 256) s_w2se[i]=w2se[i];
    __syncthreads();
    int u = t & 31, wp = t >> 5;
    int n = blockIdx.x * 8 + wp;
    const float* stin = stin_base + n * 256;
    float* stout = stout_base + n * 256;

    float n0oa=0, n0ob=0, n0ea=0, n0eb=0;
    float p00=0,p01=0,p02=0,p10=0,p11=0,p12=0,p20=0,p21=0,p22=0;
    float q00=0,q01=0,q02=0,q10=0,q11=0,q12=0,q20=0,q21=0,q22=0;

    int beg = g_rowstart[n], end = g_rowstart[n+1];
    for (int idx = beg; idx < end; idx++) {
        int e = g_csr[idx];
        int src = g_csrc[idx];
        float4 y = g_y4[e];
        float y0 = y.x, y10 = y.y, y11 = y.z, y12 = y.w;
        const float* a = g_A + src * 256;
        float eso = a[u], ese = a[32+u];
        float evo0 = a[64+u], evo1 = a[96+u], evo2 = a[128+u];
        float eve0 = a[160+u], eve1 = a[192+u], eve2 = a[224+u];
        const float* wv = g_w + (size_t)e * 320 + u;
        float w0=wv[0], w1=wv[32], w2=wv[64], w3=wv[96], w4=wv[128];
        float w5=wv[160], w6=wv[192], w7=wv[224], w8=wv[256], w9=wv[288];
        float dve = (eve0*y10 + eve1*y11 + eve2*y12) * IV3;
        float dvo = (evo0*y10 + evo1*y11 + evo2*y12) * IV3;
        float cve0 = (eve1*y12 - eve2*y11) * IV2;
        float cve1 = (eve2*y10 - eve0*y12) * IV2;
        float cve2 = (eve0*y11 - eve1*y10) * IV2;
        float cvo0 = (evo1*y12 - evo2*y11) * IV2;
        float cvo1 = (evo2*y10 - evo0*y12) * IV2;
        float cvo2 = (evo0*y11 - evo1*y10) * IV2;
        n0oa += w0 * (eso * y0);  n0ob += w1 * dve;
        n0ea += w2 * (ese * y0);  n0eb += w3 * dvo;
        float sy = w4 * ese;
        p00 += sy*y10; p01 += sy*y11; p02 += sy*y12;
        float py = w5 * y0;
        p10 += py*evo0; p11 += py*evo1; p12 += py*evo2;
        p20 += w6*cve0; p21 += w6*cve1; p22 += w6*cve2;
        float qy = w7 * eso;
        q00 += qy*y10; q01 += qy*y11; q02 += qy*y12;
        q10 += w8*cvo0; q11 += w8*cvo1; q12 += w8*cvo2;
        float ry = w9 * y0;
        q20 += ry*eve0; q21 += ry*eve1; q22 += ry*eve2;
    }
    const float S0 = IV2 * 0.25f * CX8;
    const float S1 = IV3 * 0.25f * CX96;
    n0oa*=S0; n0ob*=S0; n0ea*=S0; n0eb*=S0;
    p00*=S1;p01*=S1;p02*=S1;p10*=S1;p11*=S1;p12*=S1;p20*=S1;p21*=S1;p22*=S1;
    q00*=S1;q01*=S1;q02*=S1;q10*=S1;q11*=S1;q12*=S1;q20*=S1;q21*=S1;q22*=S1;
    float so = stin[u]*CS32, se = stin[32+u]*CS32;
    float vo0 = stin[64+u*3]*CS32, vo1 = stin[64+u*3+1]*CS32, vo2 = stin[64+u*3+2]*CS32;
    float ve0 = stin[160+u*3]*CS32, ve1 = stin[160+u*3+1]*CS32, ve2 = stin[160+u*3+2]*CS32;

    float o0o=0, oe0=0, oe1=0, oe2=0;
    float t00=0,t01=0,t02=0,t10=0,t11=0,t12=0;
#pragma unroll 4
    for (int v = 0; v < 32; v++) {
        float sov = __shfl_sync(WFULL, so, v), sev = __shfl_sync(WFULL, se, v);
        float a0 = __shfl_sync(WFULL, n0oa, v), b0 = __shfl_sync(WFULL, n0ob, v);
        float a1 = __shfl_sync(WFULL, n0ea, v), b1 = __shfl_sync(WFULL, n0eb, v);
        float vo0v = __shfl_sync(WFULL, vo0, v), vo1v = __shfl_sync(WFULL, vo1, v), vo2v = __shfl_sync(WFULL, vo2, v);
        float ve0v = __shfl_sync(WFULL, ve0, v), ve1v = __shfl_sync(WFULL, ve1, v), ve2v = __shfl_sync(WFULL, ve2, v);
        float P00=__shfl_sync(WFULL,p00,v), P01=__shfl_sync(WFULL,p01,v), P02=__shfl_sync(WFULL,p02,v);
        float P10=__shfl_sync(WFULL,p10,v), P11=__shfl_sync(WFULL,p11,v), P12=__shfl_sync(WFULL,p12,v);
        float P20=__shfl_sync(WFULL,p20,v), P21=__shfl_sync(WFULL,p21,v), P22=__shfl_sync(WFULL,p22,v);
        float Q00=__shfl_sync(WFULL,q00,v), Q01=__shfl_sync(WFULL,q01,v), Q02=__shfl_sync(WFULL,q02,v);
        float Q10=__shfl_sync(WFULL,q10,v), Q11=__shfl_sync(WFULL,q11,v), Q12=__shfl_sync(WFULL,q12,v);
        float Q20=__shfl_sync(WFULL,q20,v), Q21=__shfl_sync(WFULL,q21,v), Q22=__shfl_sync(WFULL,q22,v);

        float wa = s_wsso[v*32+u];
        float m0 = s_w2so[v*32+u], m1 = s_w2so[(32+v)*32+u];
        o0o += sov*wa + a0*m0 + b0*m1;

        float wb0 = s_wsse[v*96+u], wb1 = s_wsse[v*96+32+u], wb2 = s_wsse[v*96+64+u];
        float n0 = s_w2se[v*96+u], n1 = s_w2se[v*96+32+u], n2 = s_w2se[v*96+64+u];
        float n3 = s_w2se[(32+v)*96+u], n4 = s_w2se[(32+v)*96+32+u], n5 = s_w2se[(32+v)*96+64+u];
        oe0 += sev*wb0 + a1*n0 + b1*n3;
        oe1 += sev*wb1 + a1*n1 + b1*n4;
        oe2 += sev*wb2 + a1*n2 + b1*n5;

        float wc = s_wsvo[v*32+u];
        float r0 = s_w2vo[v*32+u], r1 = s_w2vo[(32+v)*32+u], r2 = s_w2vo[(64+v)*32+u];
        t00 += vo0v*wc + P00*r0 + P10*r1 + P20*r2;
        t01 += vo1v*wc + P01*r0 + P11*r1 + P21*r2;
        t02 += vo2v*wc + P02*r0 + P12*r1 + P22*r2;

        float wd = s_wsve[v*32+u];
        float z0 = s_w2ve[v*32+u], z1 = s_w2ve[(32+v)*32+u], z2 = s_w2ve[(64+v)*32+u];
        t10 += ve0v*wd + Q00*z0 + Q10*z1 + Q20*z2;
        t11 += ve1v*wd + Q01*z0 + Q11*z1 + Q21*z2;
        t12 += ve2v*wd + Q02*z0 + Q12*z1 + Q22*z2;
    }
    float nso = tanhf(o0o);
    float nse = oe0 / (1.0f + __expf(-oe0));
    float g1 = 1.0f / (1.0f + __expf(-oe1));
    float g2 = 1.0f / (1.0f + __expf(-oe2));
    stout[u] = nso; stout[32+u] = nse;
    stout[64+u*3] = t00*g1; stout[64+u*3+1] = t01*g1; stout[64+u*3+2] = t02*g1;
    stout[160+u*3] = t10*g2; stout[160+u*3+1] = t11*g2; stout[160+u*3+2] = t12*g2;
}

// final head lin1
__global__ void __launch_bounds__(256) k_lin1f(
    const float* __restrict__ wse, const float* __restrict__ wvo) {
    __shared__ float ws[2048];
    int t = threadIdx.x;
    for (int i = t; i < 1024; i += 256) { ws[i] = wse[i]; ws[1024+i] = wvo[i]; }
    __syncthreads();
    int u = t & 31, wp = t >> 5;
    int n = blockIdx.x * 8 + wp;
    const float* s = g_state2 + n * 256;
    float se = s[32+u];
    float vo0 = s[64+u*3], vo1 = s[64+u*3+1], vo2 = s[64+u*3+2];
    float ase=0, av0=0, av1=0, av2=0;
#pragma unroll
    for (int v = 0; v < 32; v++) {
        float b = __shfl_sync(WFULL, se, v);
        float c0 = __shfl_sync(WFULL, vo0, v), c1 = __shfl_sync(WFULL, vo1, v), c2 = __shfl_sync(WFULL, vo2, v);
        float w0 = ws[v*32+u], w1 = ws[1024+v*32+u];
        ase += b*w0; av0 += c0*w1; av1 += c1*w1; av2 += c2*w1;
    }
    float* A = g_A + n * 256;
    A[u] = ase*IS32; A[32+u] = av0*IS32; A[64+u] = av1*IS32; A[96+u] = av2*IS32;
}

__global__ void __launch_bounds__(256) k_radialf(
    const float* __restrict__ rw1, const float* __restrict__ rw2) {
    __shared__ float rw1s[1000];
    __shared__ float embs[640];
    __shared__ float hs[6400];
    __shared__ float rw2c[640];
    int t = threadIdx.x;
    int e0 = blockIdx.x * 64;
    for (int i = t; i < 1000; i += 256) rw1s[i] = rw1[i];
    for (int i = t; i < 640; i += 256) embs[i] = g_emb[e0*10 + i];
    __syncthreads();
    for (int i = t; i < 6400; i += 256) {
        int el = i / 100, j = i - el*100;
        float s = 0.0f;
#pragma unroll
        for (int k = 0; k < 10; k++) s += embs[el*10+k] * rw1s[k*100+j];
        s *= IS10;
        hs[i] = s / (1.0f + __expf(-s));
    }
    int tx = t & 31, ty = t >> 5;
    float acc0[8], acc1[8];
#pragma unroll
    for (int i = 0; i < 8; i++) { acc0[i]=0.0f; acc1[i]=0.0f; }
    for (int jc = 0; jc < 100; jc += 10) {
        __syncthreads();
        for (int i = t; i < 640; i += 256) rw2c[i] = rw2[jc*64 + i];
        __syncthreads();
#pragma unroll
        for (int jj = 0; jj < 10; jj++) {
            float w0 = rw2c[jj*64+tx], w1 = rw2c[jj*64+32+tx];
#pragma unroll
            for (int i = 0; i < 8; i++) {
                float hv = hs[(ty*8+i)*100 + jc + jj];
                acc0[i] += hv*w0; acc1[i] += hv*w1;
            }
        }
    }
#pragma unroll
    for (int i = 0; i < 8; i++) {
        float* o = g_w + (size_t)(e0 + ty*8 + i) * 64;
        o[tx] = acc0[i]*0.1f; o[32+tx] = acc1[i]*0.1f;
    }
}

__global__ void __launch_bounds__(256) k_final(
    const int* __restrict__ batch,
    const float* __restrict__ fsc, const float* __restrict__ fl2,
    float* __restrict__ out) {
    int b = blockIdx.x, t = threadIdx.x, u = t & 31, wp = t >> 5;
    // re-zero CSR counters for the next launch (inductive invariant)
    if (b < 32) g_deg[b*256 + t] = 0;
    else if (b < 64) g_cursor[(b-32)*256 + t] = 0;
    int n = b * 8 + wp;
    float na = 0, nb = 0;
    int beg = g_rowstart[n], end = g_rowstart[n+1];
    for (int idx = beg; idx < end; idx++) {
        int e = g_csr[idx];
        int src = g_csrc[idx];
        float4 y = g_y4[e];
        const float* a = g_A + src * 256;
        float ase = a[u], av0 = a[32+u], av1 = a[64+u], av2 = a[96+u];
        float w0 = g_w[(size_t)e*64 + u], w1 = g_w[(size_t)e*64 + 32 + u];
        float dvo = (av0*y.y + av1*y.z + av2*y.w) * IV3;
        na += w0 * (ase * y.x);
        nb += w1 * dvo;
    }
    const float S = IV2 * 0.25f;
    na *= S; nb *= S;
    float se = g_state2[n*256 + 32 + u];
    float val = CS32 * se * fsc[u] + CX8 * (na * fl2[u] + nb * fl2[32+u]);
#pragma unroll
    for (int off = 16; off > 0; off >>= 1)
        val += __shfl_xor_sync(WFULL, val, off);
    if (u == 0) atomicAdd(&out[batch[n]], val * OUTSC);
}

extern "C" void kernel_launch(void* const* d_in, const int* in_sizes, int n_in,
                              void* d_out, int out_size) {
    const float* x        = (const float*)d_in[0];
    const float* edge_vec = (const float*)d_in[1];
    const float* lin1_so  = (const float*)d_in[2];
    const float* lin1_se  = (const float*)d_in[3];
    const float* lin1_vo  = (const float*)d_in[4];
    const float* lin1_ve  = (const float*)d_in[5];
    const float* sc_so    = (const float*)d_in[6];
    const float* sc_se    = (const float*)d_in[7];
    const float* sc_vo    = (const float*)d_in[8];
    const float* sc_ve    = (const float*)d_in[9];
    const float* rad_w1   = (const float*)d_in[10];
    const float* rad_w2   = (const float*)d_in[11];
    const float* lin2_so  = (const float*)d_in[12];
    const float* lin2_se  = (const float*)d_in[13];
    const float* lin2_vo  = (const float*)d_in[14];
    const float* lin2_ve  = (const float*)d_in[15];
    const float* flin1_se = (const float*)d_in[16];
    const float* flin1_vo = (const float*)d_in[17];
    const float* fsc_se   = (const float*)d_in[18];
    const float* frad_w1  = (const float*)d_in[19];
    const float* frad_w2  = (const float*)d_in[20];
    const float* flin2    = (const float*)d_in[21];
    const int*   edge_src = (const int*)d_in[22];
    const int*   edge_dst = (const int*)d_in[23];
    const int*   batch    = (const int*)d_in[24];
    float* out = (float*)d_out;

    const int RAD_SMEM = SM_RAD_FLOATS * 4;
    cudaFuncSetAttribute(k_msg, cudaFuncAttributeMaxDynamicSharedMemorySize, 81920);
    cudaFuncSetAttribute(k_radial_tc, cudaFuncAttributeMaxDynamicSharedMemorySize, RAD_SMEM);

    // state buffers per layer: l0: x -> state2, l1: state2 -> state, l2: state -> state2
    float* st2; cudaGetSymbolAddress((void**)&st2, g_state2);
    float* st1; cudaGetSymbolAddress((void**)&st1, g_state);

    k_setup<<<1536, 256>>>(x, edge_vec, edge_dst, lin1_so, lin1_se, lin1_vo, lin1_ve); // 1
    k_scan<<<1, 1024>>>(out);                                                          // 2
    k_scatter<<<512, 256>>>(edge_dst, edge_src);                                       // 3
    k_radial_tc<<<1024, 640, RAD_SMEM>>>(rad_w1, rad_w2);                              // 4 (profiled)
    k_msg<<<1024, 256, 81920>>>(sc_so, sc_se, sc_vo, sc_ve,
                                lin2_so, lin2_se, lin2_vo, lin2_ve, x, st2);           // 5
    k_radial_tc<<<1024, 640, RAD_SMEM>>>(rad_w1 + 1000, rad_w2 + 32000);               // 6
    k_lin1<<<1024, 256>>>(lin1_so + 1024, lin1_se + 1024,
                          lin1_vo + 1024, lin1_ve + 1024, st2);                        // 7
    k_msg<<<1024, 256, 81920>>>(sc_so + 1024, sc_se + 3072, sc_vo + 1024, sc_ve + 1024,
                                lin2_so + 2048, lin2_se + 6144,
                                lin2_vo + 3072, lin2_ve + 3072, st2, st1);             // 8
    k_radial_tc<<<1024, 640, RAD_SMEM>>>(rad_w1 + 2000, rad_w2 + 64000);               // 9
    k_lin1<<<1024, 256>>>(lin1_so + 2048, lin1_se + 2048,
                          lin1_vo + 2048, lin1_ve + 2048, st1);                        // 10
    k_msg<<<1024, 256, 81920>>>(sc_so + 2048, sc_se + 6144, sc_vo + 2048, sc_ve + 2048,
                                lin2_so + 4096, lin2_se + 12288,
                                lin2_vo + 6144, lin2_ve + 6144, st1, st2);             // 11
    k_lin1f<<<1024, 256>>>(flin1_se, flin1_vo);                                        // 12
    k_radialf<<<2048, 256>>>(frad_w1, frad_w2);                                        // 13
    k_final<<<1024, 256>>>(batch, fsc_se, flin2, out);                                 // 14
}

// round 8
// speedup vs baseline: 1.6059x; 1.6059x over previous
#include <cuda_runtime.h>
#include <mma.h>
#include <math.h>

using namespace nvcuda;

#define EN 131072
#define NN 8192
#define WFULL 0xffffffffu

__device__ float4 g_y4[EN];
__device__ float g_emb[EN * 10];
__device__ float g_state[NN * 256];
__device__ float g_state2[NN * 256];
__device__ float g_A[NN * 256];
__device__ float g_w[(size_t)EN * 320];
__device__ float g_w2[(size_t)EN * 320];
__device__ int   g_deg[NN];
__device__ int   g_cursor[NN];
__device__ int   g_rowstart[NN + 1];
__device__ int   g_csr[EN];
__device__ int   g_csrc[EN];

#define IS32 0.17677669529663687f
#define IS10 0.31622776601683794f
#define IV2  0.7071067811865476f
#define IV3  0.5773502691896258f
#define CSC  0.3826834323650898f
#define CXC  0.9238795325112867f
#define CS32 (CSC * IS32)
#define CX8  (CXC * 0.125f)
#define CX96 (CXC * 0.10206207261596575f)
#define EMBSC 2.8234622306428f
#define OUTSC 0.044194173824159216f

__device__ __forceinline__ float to_tf32(float x) {
    float r;
    asm("cvt.rna.tf32.f32 %0, %1;" : "=f"(r) : "f"(x));
    return r;
}

// ================= setup: geometry+hist (b<512) | lin1 layer0 (b>=512) =====
__global__ void __launch_bounds__(256) k_setup(
    const float* __restrict__ x, const float* __restrict__ ev,
    const int* __restrict__ dst,
    const float* __restrict__ w1so, const float* __restrict__ w1se,
    const float* __restrict__ w1vo, const float* __restrict__ w1ve) {
    __shared__ float ws[4096];
    int b = blockIdx.x, t = threadIdx.x;
    if (b < 512) {
        int e = b * 256 + t;
        float vx = ev[e*3], vy = ev[e*3+1], vz = ev[e*3+2];
        float r = sqrtf(vx*vx + vy*vy + vz*vz);
        float inv = 1.0f / (r + 1e-12f);
        float uu = 0.5f * r - 2.0f;
        float cut;
        if (uu > 0.0f) cut = 0.0f;
        else if (uu < -1.0f) cut = 1.0f;
        else cut = 0.5f * (1.0f - cosf(3.14159265358979323846f * uu));
        const float SQ3 = 1.7320508075688772f;
        float s = SQ3 * inv * cut;
        g_y4[e] = make_float4(cut, s*vx, s*vy, s*vz);
#pragma unroll
        for (int i = 0; i < 10; i++) {
            float d = (r - (4.0f/9.0f)*(float)i) * 2.25f;
            g_emb[e*10+i] = expf(-d*d) * EMBSC;
        }
        atomicAdd(&g_deg[dst[e]], 1);
        return;
    }
    for (int i = t; i < 1024; i += 256) {
        ws[i] = w1so[i]; ws[1024+i] = w1se[i]; ws[2048+i] = w1vo[i]; ws[3072+i] = w1ve[i];
    }
    __syncthreads();
    int u = t & 31, wp = t >> 5;
    int n = (b - 512) * 8 + wp;
    const float* s = x + n * 256;
    float so = s[u], se = s[32+u];
    float vo0 = s[64+u*3], vo1 = s[64+u*3+1], vo2 = s[64+u*3+2];
    float ve0 = s[160+u*3], ve1 = s[160+u*3+1], ve2 = s[160+u*3+2];
    float aso=0, ase=0, avo0=0, avo1=0, avo2=0, ave0=0, ave1=0, ave2=0;
#pragma unroll
    for (int v = 0; v < 32; v++) {
        float a = __shfl_sync(WFULL, so, v), bb = __shfl_sync(WFULL, se, v);
        float c0 = __shfl_sync(WFULL, vo0, v), c1 = __shfl_sync(WFULL, vo1, v), c2 = __shfl_sync(WFULL, vo2, v);
        float d0 = __shfl_sync(WFULL, ve0, v), d1 = __shfl_sync(WFULL, ve1, v), d2 = __shfl_sync(WFULL, ve2, v);
        float w0 = ws[v*32+u], w1 = ws[1024+v*32+u], w2 = ws[2048+v*32+u], w3 = ws[3072+v*32+u];
        aso += a*w0; ase += bb*w1;
        avo0 += c0*w2; avo1 += c1*w2; avo2 += c2*w2;
        ave0 += d0*w3; ave1 += d1*w3; ave2 += d2*w3;
    }
    float* A = g_A + n * 256;
    A[u] = aso*IS32; A[32+u] = ase*IS32;
    A[64+u] = avo0*IS32; A[96+u] = avo1*IS32; A[128+u] = avo2*IS32;
    A[160+u] = ave0*IS32; A[192+u] = ave1*IS32; A[224+u] = ave2*IS32;
}

__global__ void k_scan(float* __restrict__ out) {
    __shared__ int part[1024];
    int t = threadIdx.x;
    if (t < 16) out[t] = 0.0f;
    int loc[8]; int run = 0;
#pragma unroll
    for (int i = 0; i < 8; i++) { loc[i] = run; run += g_deg[t*8+i]; }
    part[t] = run;
    __syncthreads();
    for (int off = 1; off < 1024; off <<= 1) {
        int xv = (t >= off) ? part[t-off] : 0;
        __syncthreads();
        part[t] += xv;
        __syncthreads();
    }
    int base = (t > 0) ? part[t-1] : 0;
#pragma unroll
    for (int i = 0; i < 8; i++) g_rowstart[t*8+i] = base + loc[i];
    if (t == 1023) g_rowstart[NN] = EN;
}

// node linear-1 (layers 1,2)
__global__ void __launch_bounds__(256) k_lin1(
    const float* __restrict__ w1so, const float* __restrict__ w1se,
    const float* __restrict__ w1vo, const float* __restrict__ w1ve,
    const float* __restrict__ stin_base) {
    __shared__ float ws[4096];
    int t = threadIdx.x;
    for (int i = t; i < 1024; i += 256) {
        ws[i] = w1so[i]; ws[1024+i] = w1se[i]; ws[2048+i] = w1vo[i]; ws[3072+i] = w1ve[i];
    }
    __syncthreads();
    int u = t & 31, wp = t >> 5;
    int n = blockIdx.x * 8 + wp;
    const float* s = stin_base + n * 256;
    float so = s[u], se = s[32+u];
    float vo0 = s[64+u*3], vo1 = s[64+u*3+1], vo2 = s[64+u*3+2];
    float ve0 = s[160+u*3], ve1 = s[160+u*3+1], ve2 = s[160+u*3+2];
    float aso=0, ase=0, avo0=0, avo1=0, avo2=0, ave0=0, ave1=0, ave2=0;
#pragma unroll
    for (int v = 0; v < 32; v++) {
        float a = __shfl_sync(WFULL, so, v), b = __shfl_sync(WFULL, se, v);
        float c0 = __shfl_sync(WFULL, vo0, v), c1 = __shfl_sync(WFULL, vo1, v), c2 = __shfl_sync(WFULL, vo2, v);
        float d0 = __shfl_sync(WFULL, ve0, v), d1 = __shfl_sync(WFULL, ve1, v), d2 = __shfl_sync(WFULL, ve2, v);
        float w0 = ws[v*32+u], w1 = ws[1024+v*32+u], w2 = ws[2048+v*32+u], w3 = ws[3072+v*32+u];
        aso += a*w0; ase += b*w1;
        avo0 += c0*w2; avo1 += c1*w2; avo2 += c2*w2;
        ave0 += d0*w3; ave1 += d1*w3; ave2 += d2*w3;
    }
    float* A = g_A + n * 256;
    A[u] = aso*IS32; A[32+u] = ase*IS32;
    A[64+u] = avo0*IS32; A[96+u] = avo1*IS32; A[128+u] = avo2*IS32;
    A[160+u] = ave0*IS32; A[192+u] = ave1*IS32; A[224+u] = ave2*IS32;
}

// ============== device body: radial tf32 GEMM (R4 config, 512 thr) =========
#define LDH 104
#define LDB 324
#define SM_B (128 * LDH)
#define SM_RW1 (SM_B + 104 * LDB)
#define SM_EMB (SM_RW1 + 1000)
#define SM_RAD_FLOATS (SM_EMB + 1280)

__device__ __forceinline__ void dev_radial(
    const float* __restrict__ rw1, const float* __restrict__ rw2,
    float* __restrict__ wout, int rb, float* sh) {
    float* h_s   = sh;
    float* B_s   = sh + SM_B;
    float* rw1_s = sh + SM_RW1;
    float* emb_s = sh + SM_EMB;
    int t = threadIdx.x;
    int e0 = rb * 128;

    for (int i = t; i < 1000; i += 512) rw1_s[i] = rw1[i];
    for (int i = t; i < 1280; i += 512) emb_s[i] = g_emb[e0*10 + i];
    for (int i = t; i < 104*320; i += 512) {
        int k = i / 320, n = i - k*320;
        B_s[k*LDB + n] = (k < 100) ? to_tf32(rw2[k*320 + n]) : 0.0f;
    }
    __syncthreads();
    for (int i = t; i < 12800; i += 512) {
        int e = i / 100, j = i - e*100;
        float s = 0.0f;
#pragma unroll
        for (int k = 0; k < 10; k++) s += emb_s[e*10+k] * rw1_s[k*100+j];
        s *= IS10;
        h_s[e*LDH + j] = to_tf32(s / (1.0f + __expf(-s)));
    }
    {
        int e = t >> 2, c = t & 3;
        h_s[e*LDH + 100 + c] = 0.0f;
    }
    __syncthreads();

    int w = t >> 5;
    int mg = w >> 1;   // 0..7
    int ng = w & 1;    // 0..1

    wmma::fragment<wmma::accumulator, 16, 16, 8, float> c[10];
#pragma unroll
    for (int i = 0; i < 10; i++) wmma::fill_fragment(c[i], 0.0f);

    for (int kt = 0; kt < 13; kt++) {
        wmma::fragment<wmma::matrix_a, 16, 16, 8, wmma::precision::tf32, wmma::row_major> a;
        wmma::load_matrix_sync(a, h_s + (mg*16)*LDH + kt*8, LDH);
#pragma unroll
        for (int ni = 0; ni < 10; ni++) {
            wmma::fragment<wmma::matrix_b, 16, 16, 8, wmma::precision::tf32, wmma::row_major> b;
            wmma::load_matrix_sync(b, B_s + (kt*8)*LDB + ng*160 + ni*16, LDB);
            wmma::mma_sync(c[ni], a, b, c[ni]);
        }
    }
#pragma unroll
    for (int ni = 0; ni < 10; ni++) {
#pragma unroll
        for (int i = 0; i < c[ni].num_elements; i++) c[ni].x[i] *= 0.1f;
        wmma::store_matrix_sync(
            wout + (size_t)(e0 + mg*16) * 320 + ng*160 + ni*16,
            c[ni], 320, wmma::mem_row_major);
    }
}

// ============== device body: dst-centric msg + node update (512 thr) =======
__device__ __forceinline__ void dev_msg(
    const float* __restrict__ wsso, const float* __restrict__ wsse,
    const float* __restrict__ wsvo, const float* __restrict__ wsve,
    const float* __restrict__ w2so, const float* __restrict__ w2se,
    const float* __restrict__ w2vo, const float* __restrict__ w2ve,
    const float* __restrict__ stin_base, float* __restrict__ stout_base,
    const float* __restrict__ wbuf, int mb, float* sm) {
    float* s_wsso = sm;
    float* s_wsse = sm + 1024;
    float* s_wsvo = sm + 4096;
    float* s_wsve = sm + 5120;
    float* s_w2so = sm + 6144;
    float* s_w2se = sm + 8192;
    float* s_w2vo = sm + 14336;
    float* s_w2ve = sm + 17408;
    int t = threadIdx.x;
    for (int i = t; i < 1024; i += 512) { s_wsso[i]=wsso[i]; s_wsvo[i]=wsvo[i]; s_wsve[i]=wsve[i]; }
    for (int i = t; i < 3072; i += 512) { s_wsse[i]=wsse[i]; s_w2vo[i]=w2vo[i]; s_w2ve[i]=w2ve[i]; }
    for (int i = t; i < 2048; i += 512) s_w2so[i]=w2so[i];
    for (int i = t; i < 6144; i += 512) s_w2se[i]=w2se[i];
    __syncthreads();
    int u = t & 31, wp = t >> 5;
    int n = mb * 16 + wp;
    const float* stin = stin_base + n * 256;
    float* stout = stout_base + n * 256;

    float n0oa=0, n0ob=0, n0ea=0, n0eb=0;
    float p00=0,p01=0,p02=0,p10=0,p11=0,p12=0,p20=0,p21=0,p22=0;
    float q00=0,q01=0,q02=0,q10=0,q11=0,q12=0,q20=0,q21=0,q22=0;

    int beg = g_rowstart[n], end = g_rowstart[n+1];
    for (int idx = beg; idx < end; idx++) {
        int e = g_csr[idx];
        int src = g_csrc[idx];
        float4 y = g_y4[e];
        float y0 = y.x, y10 = y.y, y11 = y.z, y12 = y.w;
        const float* a = g_A + src * 256;
        float eso = a[u], ese = a[32+u];
        float evo0 = a[64+u], evo1 = a[96+u], evo2 = a[128+u];
        float eve0 = a[160+u], eve1 = a[192+u], eve2 = a[224+u];
        const float* wv = wbuf + (size_t)e * 320 + u;
        float w0=wv[0], w1=wv[32], w2=wv[64], w3=wv[96], w4=wv[128];
        float w5=wv[160], w6=wv[192], w7=wv[224], w8=wv[256], w9=wv[288];
        float dve = (eve0*y10 + eve1*y11 + eve2*y12) * IV3;
        float dvo = (evo0*y10 + evo1*y11 + evo2*y12) * IV3;
        float cve0 = (eve1*y12 - eve2*y11) * IV2;
        float cve1 = (eve2*y10 - eve0*y12) * IV2;
        float cve2 = (eve0*y11 - eve1*y10) * IV2;
        float cvo0 = (evo1*y12 - evo2*y11) * IV2;
        float cvo1 = (evo2*y10 - evo0*y12) * IV2;
        float cvo2 = (evo0*y11 - evo1*y10) * IV2;
        n0oa += w0 * (eso * y0);  n0ob += w1 * dve;
        n0ea += w2 * (ese * y0);  n0eb += w3 * dvo;
        float sy = w4 * ese;
        p00 += sy*y10; p01 += sy*y11; p02 += sy*y12;
        float py = w5 * y0;
        p10 += py*evo0; p11 += py*evo1; p12 += py*evo2;
        p20 += w6*cve0; p21 += w6*cve1; p22 += w6*cve2;
        float qy = w7 * eso;
        q00 += qy*y10; q01 += qy*y11; q02 += qy*y12;
        q10 += w8*cvo0; q11 += w8*cvo1; q12 += w8*cvo2;
        float ry = w9 * y0;
        q20 += ry*eve0; q21 += ry*eve1; q22 += ry*eve2;
    }
    const float S0 = IV2 * 0.25f * CX8;
    const float S1 = IV3 * 0.25f * CX96;
    n0oa*=S0; n0ob*=S0; n0ea*=S0; n0eb*=S0;
    p00*=S1;p01*=S1;p02*=S1;p10*=S1;p11*=S1;p12*=S1;p20*=S1;p21*=S1;p22*=S1;
    q00*=S1;q01*=S1;q02*=S1;q10*=S1;q11*=S1;q12*=S1;q20*=S1;q21*=S1;q22*=S1;
    float so = stin[u]*CS32, se = stin[32+u]*CS32;
    float vo0 = stin[64+u*3]*CS32, vo1 = stin[64+u*3+1]*CS32, vo2 = stin[64+u*3+2]*CS32;
    float ve0 = stin[160+u*3]*CS32, ve1 = stin[160+u*3+1]*CS32, ve2 = stin[160+u*3+2]*CS32;

    float o0o=0, oe0=0, oe1=0, oe2=0;
    float t00=0,t01=0,t02=0,t10=0,t11=0,t12=0;
#pragma unroll 4
    for (int v = 0; v < 32; v++) {
        float sov = __shfl_sync(WFULL, so, v), sev = __shfl_sync(WFULL, se, v);
        float a0 = __shfl_sync(WFULL, n0oa, v), b0 = __shfl_sync(WFULL, n0ob, v);
        float a1 = __shfl_sync(WFULL, n0ea, v), b1 = __shfl_sync(WFULL, n0eb, v);
        float vo0v = __shfl_sync(WFULL, vo0, v), vo1v = __shfl_sync(WFULL, vo1, v), vo2v = __shfl_sync(WFULL, vo2, v);
        float ve0v = __shfl_sync(WFULL, ve0, v), ve1v = __shfl_sync(WFULL, ve1, v), ve2v = __shfl_sync(WFULL, ve2, v);
        float P00=__shfl_sync(WFULL,p00,v), P01=__shfl_sync(WFULL,p01,v), P02=__shfl_sync(WFULL,p02,v);
        float P10=__shfl_sync(WFULL,p10,v), P11=__shfl_sync(WFULL,p11,v), P12=__shfl_sync(WFULL,p12,v);
        float P20=__shfl_sync(WFULL,p20,v), P21=__shfl_sync(WFULL,p21,v), P22=__shfl_sync(WFULL,p22,v);
        float Q00=__shfl_sync(WFULL,q00,v), Q01=__shfl_sync(WFULL,q01,v), Q02=__shfl_sync(WFULL,q02,v);
        float Q10=__shfl_sync(WFULL,q10,v), Q11=__shfl_sync(WFULL,q11,v), Q12=__shfl_sync(WFULL,q12,v);
        float Q20=__shfl_sync(WFULL,q20,v), Q21=__shfl_sync(WFULL,q21,v), Q22=__shfl_sync(WFULL,q22,v);

        float wa = s_wsso[v*32+u];
        float m0 = s_w2so[v*32+u], m1 = s_w2so[(32+v)*32+u];
        o0o += sov*wa + a0*m0 + b0*m1;

        float wb0 = s_wsse[v*96+u], wb1 = s_wsse[v*96+32+u], wb2 = s_wsse[v*96+64+u];
        float n0 = s_w2se[v*96+u], n1 = s_w2se[v*96+32+u], n2 = s_w2se[v*96+64+u];
        float n3 = s_w2se[(32+v)*96+u], n4 = s_w2se[(32+v)*96+32+u], n5 = s_w2se[(32+v)*96+64+u];
        oe0 += sev*wb0 + a1*n0 + b1*n3;
        oe1 += sev*wb1 + a1*n1 + b1*n4;
        oe2 += sev*wb2 + a1*n2 + b1*n5;

        float wc = s_wsvo[v*32+u];
        float r0 = s_w2vo[v*32+u], r1 = s_w2vo[(32+v)*32+u], r2 = s_w2vo[(64+v)*32+u];
        t00 += vo0v*wc + P00*r0 + P10*r1 + P20*r2;
        t01 += vo1v*wc + P01*r0 + P11*r1 + P21*r2;
        t02 += vo2v*wc + P02*r0 + P12*r1 + P22*r2;

        float wd = s_wsve[v*32+u];
        float z0 = s_w2ve[v*32+u], z1 = s_w2ve[(32+v)*32+u], z2 = s_w2ve[(64+v)*32+u];
        t10 += ve0v*wd + Q00*z0 + Q10*z1 + Q20*z2;
        t11 += ve1v*wd + Q01*z0 + Q11*z1 + Q21*z2;
        t12 += ve2v*wd + Q02*z0 + Q12*z1 + Q22*z2;
    }
    float nso = tanhf(o0o);
    float nse = oe0 / (1.0f + __expf(-oe0));
    float g1 = 1.0f / (1.0f + __expf(-oe1));
    float g2 = 1.0f / (1.0f + __expf(-oe2));
    stout[u] = nso; stout[32+u] = nse;
    stout[64+u*3] = t00*g1; stout[64+u*3+1] = t01*g1; stout[64+u*3+2] = t02*g1;
    stout[160+u*3] = t10*g2; stout[160+u*3+1] = t11*g2; stout[160+u*3+2] = t12*g2;
}

// ============== device body: final-head radial (512 thr, 128 edges) ========
__device__ __forceinline__ void dev_radialf(
    const float* __restrict__ rw1, const float* __restrict__ rw2,
    float* __restrict__ wout, int rb, float* sh) {
    float* rw1s = sh;            // 1000
    float* embs = sh + 1000;     // 1280
    float* hs   = sh + 2280;     // 12800
    float* rw2c = sh + 15080;    // 640
    int t = threadIdx.x;
    int e0 = rb * 128;
    for (int i = t; i < 1000; i += 512) rw1s[i] = rw1[i];
    for (int i = t; i < 1280; i += 512) embs[i] = g_emb[e0*10 + i];
    __syncthreads();
    for (int i = t; i < 12800; i += 512) {
        int el = i / 100, j = i - el*100;
        float s = 0.0f;
#pragma unroll
        for (int k = 0; k < 10; k++) s += embs[el*10+k] * rw1s[k*100+j];
        s *= IS10;
        hs[i] = s / (1.0f + __expf(-s));
    }
    int tx = t & 31, ty = t >> 5;   // 16 warps x 8 rows = 128 edges
    float acc0[8], acc1[8];
#pragma unroll
    for (int i = 0; i < 8; i++) { acc0[i]=0.0f; acc1[i]=0.0f; }
    for (int jc = 0; jc < 100; jc += 10) {
        __syncthreads();
        for (int i = t; i < 640; i += 512) rw2c[i] = rw2[jc*64 + i];
        __syncthreads();
#pragma unroll
        for (int jj = 0; jj < 10; jj++) {
            float w0 = rw2c[jj*64+tx], w1 = rw2c[jj*64+32+tx];
#pragma unroll
            for (int i = 0; i < 8; i++) {
                float hv = hs[(ty*8+i)*100 + jc + jj];
                acc0[i] += hv*w0; acc1[i] += hv*w1;
            }
        }
    }
#pragma unroll
    for (int i = 0; i < 8; i++) {
        float* o = wout + (size_t)(e0 + ty*8 + i) * 64;
        o[tx] = acc0[i]*0.1f; o[32+tx] = acc1[i]*0.1f;
    }
}

// ================= fused launches ==========================================
// F1: radial layer0 -> g_w  (1024 blocks) + scatter (256 blocks)
__global__ void __launch_bounds__(512) k_fused_rs(
    const float* __restrict__ rw1, const float* __restrict__ rw2,
    const int* __restrict__ dst, const int* __restrict__ src) {
    extern __shared__ float sh[];
    int b = blockIdx.x;
    if ((b % 5) == 4) {
        int e = (b / 5) * 512 + threadIdx.x;
        int d = dst[e];
        int pos = atomicAdd(&g_cursor[d], 1);
        int slot = g_rowstart[d] + pos;
        g_csr[slot] = e;
        g_csrc[slot] = src[e];
        return;
    }
    int rb = (b / 5) * 4 + (b % 5);
    dev_radial(rw1, rw2, g_w, rb, sh);
}

// F2/F3: msg layer l (512 blocks, reads win) + radial layer l+1 -> wnext (1024 blocks)
__global__ void __launch_bounds__(512) k_fused_rm(
    const float* __restrict__ rw1, const float* __restrict__ rw2,
    float* __restrict__ wnext,
    const float* __restrict__ wsso, const float* __restrict__ wsse,
    const float* __restrict__ wsvo, const float* __restrict__ wsve,
    const float* __restrict__ w2so, const float* __restrict__ w2se,
    const float* __restrict__ w2vo, const float* __restrict__ w2ve,
    const float* __restrict__ stin, float* __restrict__ stout,
    const float* __restrict__ win) {
    extern __shared__ float sh[];
    int b = blockIdx.x;
    if ((b % 3) == 2) {
        dev_msg(wsso, wsse, wsvo, wsve, w2so, w2se, w2vo, w2ve,
                stin, stout, win, b / 3, sh);
        return;
    }
    int rb = (b / 3) * 2 + (b % 3);
    dev_radial(rw1, rw2, wnext, rb, sh);
}

// F4: msg layer2 (512 blocks, reads g_w) + final-head radial -> g_w2 (1024 blocks)
__global__ void __launch_bounds__(512) k_fused_mf(
    const float* __restrict__ frw1, const float* __restrict__ frw2,
    const float* __restrict__ wsso, const float* __restrict__ wsse,
    const float* __restrict__ wsvo, const float* __restrict__ wsve,
    const float* __restrict__ w2so, const float* __restrict__ w2se,
    const float* __restrict__ w2vo, const float* __restrict__ w2ve,
    const float* __restrict__ stin, float* __restrict__ stout) {
    extern __shared__ float sh[];
    int b = blockIdx.x;
    if ((b % 3) == 2) {
        dev_msg(wsso, wsse, wsvo, wsve, w2so, w2se, w2vo, w2ve,
                stin, stout, g_w, b / 3, sh);
        return;
    }
    int rb = (b / 3) * 2 + (b % 3);
    dev_radialf(frw1, frw2, g_w2, rb, sh);
}

// final head lin1
__global__ void __launch_bounds__(256) k_lin1f(
    const float* __restrict__ wse, const float* __restrict__ wvo) {
    __shared__ float ws[2048];
    int t = threadIdx.x;
    for (int i = t; i < 1024; i += 256) { ws[i] = wse[i]; ws[1024+i] = wvo[i]; }
    __syncthreads();
    int u = t & 31, wp = t >> 5;
    int n = blockIdx.x * 8 + wp;
    const float* s = g_state2 + n * 256;
    float se = s[32+u];
    float vo0 = s[64+u*3], vo1 = s[64+u*3+1], vo2 = s[64+u*3+2];
    float ase=0, av0=0, av1=0, av2=0;
#pragma unroll
    for (int v = 0; v < 32; v++) {
        float b = __shfl_sync(WFULL, se, v);
        float c0 = __shfl_sync(WFULL, vo0, v), c1 = __shfl_sync(WFULL, vo1, v), c2 = __shfl_sync(WFULL, vo2, v);
        float w0 = ws[v*32+u], w1 = ws[1024+v*32+u];
        ase += b*w0; av0 += c0*w1; av1 += c1*w1; av2 += c2*w1;
    }
    float* A = g_A + n * 256;
    A[u] = ase*IS32; A[32+u] = av0*IS32; A[64+u] = av1*IS32; A[96+u] = av2*IS32;
}

__global__ void __launch_bounds__(256) k_final(
    const int* __restrict__ batch,
    const float* __restrict__ fsc, const float* __restrict__ fl2,
    float* __restrict__ out) {
    int b = blockIdx.x, t = threadIdx.x, u = t & 31, wp = t >> 5;
    if (b < 32) g_deg[b*256 + t] = 0;
    else if (b < 64) g_cursor[(b-32)*256 + t] = 0;
    int n = b * 8 + wp;
    float na = 0, nb = 0;
    int beg = g_rowstart[n], end = g_rowstart[n+1];
    for (int idx = beg; idx < end; idx++) {
        int e = g_csr[idx];
        int src = g_csrc[idx];
        float4 y = g_y4[e];
        const float* a = g_A + src * 256;
        float ase = a[u], av0 = a[32+u], av1 = a[64+u], av2 = a[96+u];
        float w0 = g_w2[(size_t)e*64 + u], w1 = g_w2[(size_t)e*64 + 32 + u];
        float dvo = (av0*y.y + av1*y.z + av2*y.w) * IV3;
        na += w0 * (ase * y.x);
        nb += w1 * dvo;
    }
    const float S = IV2 * 0.25f;
    na *= S; nb *= S;
    float se = g_state2[n*256 + 32 + u];
    float val = CS32 * se * fsc[u] + CX8 * (na * fl2[u] + nb * fl2[32+u]);
#pragma unroll
    for (int off = 16; off > 0; off >>= 1)
        val += __shfl_xor_sync(WFULL, val, off);
    if (u == 0) atomicAdd(&out[batch[n]], val * OUTSC);
}

extern "C" void kernel_launch(void* const* d_in, const int* in_sizes, int n_in,
                              void* d_out, int out_size) {
    const float* x        = (const float*)d_in[0];
    const float* edge_vec = (const float*)d_in[1];
    const float* lin1_so  = (const float*)d_in[2];
    const float* lin1_se  = (const float*)d_in[3];
    const float* lin1_vo  = (const float*)d_in[4];
    const float* lin1_ve  = (const float*)d_in[5];
    const float* sc_so    = (const float*)d_in[6];
    const float* sc_se    = (const float*)d_in[7];
    const float* sc_vo    = (const float*)d_in[8];
    const float* sc_ve    = (const float*)d_in[9];
    const float* rad_w1   = (const float*)d_in[10];
    const float* rad_w2   = (const float*)d_in[11];
    const float* lin2_so  = (const float*)d_in[12];
    const float* lin2_se  = (const float*)d_in[13];
    const float* lin2_vo  = (const float*)d_in[14];
    const float* lin2_ve  = (const float*)d_in[15];
    const float* flin1_se = (const float*)d_in[16];
    const float* flin1_vo = (const float*)d_in[17];
    const float* fsc_se   = (const float*)d_in[18];
    const float* frad_w1  = (const float*)d_in[19];
    const float* frad_w2  = (const float*)d_in[20];
    const float* flin2    = (const float*)d_in[21];
    const int*   edge_src = (const int*)d_in[22];
    const int*   edge_dst = (const int*)d_in[23];
    const int*   batch    = (const int*)d_in[24];
    float* out = (float*)d_out;

    const int RAD_SMEM = SM_RAD_FLOATS * 4;   // 197152 B
    cudaFuncSetAttribute(k_fused_rs, cudaFuncAttributeMaxDynamicSharedMemorySize, RAD_SMEM);
    cudaFuncSetAttribute(k_fused_rm, cudaFuncAttributeMaxDynamicSharedMemorySize, RAD_SMEM);
    cudaFuncSetAttribute(k_fused_mf, cudaFuncAttributeMaxDynamicSharedMemorySize, 81920);

    float* st2; cudaGetSymbolAddress((void**)&st2, g_state2);
    float* st1; cudaGetSymbolAddress((void**)&st1, g_state);
    float* wA;  cudaGetSymbolAddress((void**)&wA, g_w);
    float* wB;  cudaGetSymbolAddress((void**)&wB, g_w2);

    k_setup<<<1536, 256>>>(x, edge_vec, edge_dst, lin1_so, lin1_se, lin1_vo, lin1_ve); // 1
    k_scan<<<1, 1024>>>(out);                                                          // 2
    k_fused_rs<<<1280, 512, RAD_SMEM>>>(rad_w1, rad_w2, edge_dst, edge_src);           // 3
    k_fused_rm<<<1536, 512, RAD_SMEM>>>(rad_w1 + 1000, rad_w2 + 32000, wB,
                                        sc_so, sc_se, sc_vo, sc_ve,
                                        lin2_so, lin2_se, lin2_vo, lin2_ve,
                                        x, st2, wA);                                   // 4 (profiled)
    k_lin1<<<1024, 256>>>(lin1_so + 1024, lin1_se + 1024,
                          lin1_vo + 1024, lin1_ve + 1024, st2);                        // 5
    k_fused_rm<<<1536, 512, RAD_SMEM>>>(rad_w1 + 2000, rad_w2 + 64000, wA,
                                        sc_so + 1024, sc_se + 3072, sc_vo + 1024, sc_ve + 1024,
                                        lin2_so + 2048, lin2_se + 6144,
                                        lin2_vo + 3072, lin2_ve + 3072,
                                        st2, st1, wB);                                 // 6
    k_lin1<<<1024, 256>>>(lin1_so + 2048, lin1_se + 2048,
                          lin1_vo + 2048, lin1_ve + 2048, st1);                        // 7
    k_fused_mf<<<1536, 512, 81920>>>(frad_w1, frad_w2,
                                     sc_so + 2048, sc_se + 6144, sc_vo + 2048, sc_ve + 2048,
                                     lin2_so + 4096, lin2_se + 12288,
                                     lin2_vo + 6144, lin2_ve + 6144,
                                     st1, st2);                                        // 8
    k_lin1f<<<1024, 256>>>(flin1_se, flin1_vo);                                        // 9
    k_final<<<1024, 256>>>(batch, fsc_se, flin2, out);                                 // 10
}

// round 13
// speedup vs baseline: 2.5818x; 1.6077x over previous
#include <cuda_runtime.h>
#include <math.h>

#define EN 131072
#define NN 8192
#define NK 8192
#define WFULL 0xffffffffu

__device__ float4 g_y4[EN];
__device__ float2 g_rl[EN];
__device__ float g_state[NN * 256];
__device__ float g_state2[NN * 256];
__device__ float g_A[NN * 256];
__device__ float g_tab[3 * NK * 320];
__device__ float g_tabf[NK * 64];
__device__ int   g_deg[NN];
__device__ int   g_cursor[NN];
__device__ int   g_rowstart[NN + 1];
__device__ int   g_csr[EN];
__device__ int   g_csrc[EN];

#define IS32 0.17677669529663687f
#define IS10 0.31622776601683794f
#define IV2  0.7071067811865476f
#define IV3  0.5773502691896258f
#define CSC  0.3826834323650898f
#define CXC  0.9238795325112867f
#define CS32 (CSC * IS32)
#define CX8  (CXC * 0.125f)
#define CX96 (CXC * 0.10206207261596575f)
#define EMBSC 2.8234622306428f
#define OUTSC 0.044194173824159216f
#define RDELTA (8.0f / 8191.0f)
#define RINV   (8191.0f / 8.0f)

// table builder: 32 knots per block, ncol outputs per knot
__device__ __forceinline__ void dev_table(
    const float* __restrict__ rw1, const float* __restrict__ rw2,
    float* __restrict__ tab, int ncol, int knot0, float* sbuf) {
    float* h  = sbuf;          // 3200
    float* em = sbuf + 3200;   // 320
    int t = threadIdx.x;
    for (int i = t; i < 320; i += 256) {   // strided fill: all 320 entries covered by 256 threads
        int k = i / 10, j = i - k * 10;
        float r = (float)(knot0 + k) * RDELTA;
        float d = (r - (float)j * (4.0f/9.0f)) * 2.25f;
        em[i] = expf(-d*d) * EMBSC;
    }
    __syncthreads();
    for (int i = t; i < 3200; i += 256) {
        int k = i / 100, j = i - k * 100;
        float s = 0.0f;
#pragma unroll
        for (int m = 0; m < 10; m++) s += em[k*10+m] * rw1[m*100+j];
        s *= IS10;
        h[i] = s / (1.0f + __expf(-s));
    }
    __syncthreads();
    int total = 32 * ncol;
    for (int i = t; i < total; i += 256) {
        int k = i / ncol, col = i - k * ncol;
        float acc = 0.0f;
#pragma unroll 4
        for (int m = 0; m < 100; m++) acc += h[k*100+m] * rw2[m*ncol+col];
        tab[(size_t)(knot0 + k) * ncol + col] = acc * 0.1f;
    }
}

// ===== k_setup: geom+hist (b<512) | lin1 layer0 (512..1535) | tables (1536..2559)
__global__ void __launch_bounds__(256) k_setup(
    const float* __restrict__ x, const float* __restrict__ ev,
    const int* __restrict__ dst,
    const float* __restrict__ w1so, const float* __restrict__ w1se,
    const float* __restrict__ w1vo, const float* __restrict__ w1ve,
    const float* __restrict__ rw1, const float* __restrict__ rw2,
    const float* __restrict__ frw1, const float* __restrict__ frw2) {
    __shared__ float sbuf[4096];
    int b = blockIdx.x, t = threadIdx.x;
    if (b < 512) {
        int e = b * 256 + t;
        float vx = ev[e*3], vy = ev[e*3+1], vz = ev[e*3+2];
        float r = sqrtf(vx*vx + vy*vy + vz*vz);
        float inv = 1.0f / (r + 1e-12f);
        float uu = 0.5f * r - 2.0f;
        float cut;
        if (uu > 0.0f) cut = 0.0f;
        else if (uu < -1.0f) cut = 1.0f;
        else cut = 0.5f * (1.0f - cosf(3.14159265358979323846f * uu));
        const float SQ3 = 1.7320508075688772f;
        float s = SQ3 * inv * cut;
        g_y4[e] = make_float4(cut, s*vx, s*vy, s*vz);
        float xq = r * RINV;
        int ri = (int)xq;
        if (ri > NK - 2) ri = NK - 2;
        float rf = xq - (float)ri;
        if (rf > 1.0f) rf = 1.0f;
        g_rl[e] = make_float2((float)ri, rf);
        atomicAdd(&g_deg[dst[e]], 1);
        return;
    }
    if (b >= 1536) {
        int tb = b - 1536;
        if (tb < 768) {
            int layer = tb >> 8, kg = tb & 255;
            dev_table(rw1 + layer*1000, rw2 + layer*32000,
                      g_tab + (size_t)layer*NK*320, 320, kg*32, sbuf);
        } else {
            int kg = tb - 768;
            dev_table(frw1, frw2, g_tabf, 64, kg*32, sbuf);
        }
        return;
    }
    // lin1 layer 0
    float* ws = sbuf;
    for (int i = t; i < 1024; i += 256) {
        ws[i] = w1so[i]; ws[1024+i] = w1se[i]; ws[2048+i] = w1vo[i]; ws[3072+i] = w1ve[i];
    }
    __syncthreads();
    int u = t & 31, wp = t >> 5;
    int n = (b - 512) * 8 + wp;
    const float* s = x + n * 256;
    float so = s[u], se = s[32+u];
    float vo0 = s[64+u*3], vo1 = s[64+u*3+1], vo2 = s[64+u*3+2];
    float ve0 = s[160+u*3], ve1 = s[160+u*3+1], ve2 = s[160+u*3+2];
    float aso=0, ase=0, avo0=0, avo1=0, avo2=0, ave0=0, ave1=0, ave2=0;
#pragma unroll
    for (int v = 0; v < 32; v++) {
        float a = __shfl_sync(WFULL, so, v), bb = __shfl_sync(WFULL, se, v);
        float c0 = __shfl_sync(WFULL, vo0, v), c1 = __shfl_sync(WFULL, vo1, v), c2 = __shfl_sync(WFULL, vo2, v);
        float d0 = __shfl_sync(WFULL, ve0, v), d1 = __shfl_sync(WFULL, ve1, v), d2 = __shfl_sync(WFULL, ve2, v);
        float w0 = ws[v*32+u], w1 = ws[1024+v*32+u], w2 = ws[2048+v*32+u], w3 = ws[3072+v*32+u];
        aso += a*w0; ase += bb*w1;
        avo0 += c0*w2; avo1 += c1*w2; avo2 += c2*w2;
        ave0 += d0*w3; ave1 += d1*w3; ave2 += d2*w3;
    }
    float* A = g_A + n * 256;
    A[u] = aso*IS32; A[32+u] = ase*IS32;
    A[64+u] = avo0*IS32; A[96+u] = avo1*IS32; A[128+u] = avo2*IS32;
    A[160+u] = ave0*IS32; A[192+u] = ave1*IS32; A[224+u] = ave2*IS32;
}

__global__ void k_scan(float* __restrict__ out) {
    __shared__ int part[1024];
    int t = threadIdx.x;
    if (t < 16) out[t] = 0.0f;
    int loc[8]; int run = 0;
#pragma unroll
    for (int i = 0; i < 8; i++) { loc[i] = run; run += g_deg[t*8+i]; }
    part[t] = run;
    __syncthreads();
    for (int off = 1; off < 1024; off <<= 1) {
        int xv = (t >= off) ? part[t-off] : 0;
        __syncthreads();
        part[t] += xv;
        __syncthreads();
    }
    int base = (t > 0) ? part[t-1] : 0;
#pragma unroll
    for (int i = 0; i < 8; i++) g_rowstart[t*8+i] = base + loc[i];
    if (t == 1023) g_rowstart[NN] = EN;
}

__global__ void k_scatter(const int* __restrict__ dst, const int* __restrict__ src) {
    int e = blockIdx.x * blockDim.x + threadIdx.x;
    if (e >= EN) return;
    int d = dst[e];
    int pos = atomicAdd(&g_cursor[d], 1);
    int slot = g_rowstart[d] + pos;
    g_csr[slot] = e;
    g_csrc[slot] = src[e];
}

// node linear-1 (layers 1,2)
__global__ void __launch_bounds__(256) k_lin1(
    const float* __restrict__ w1so, const float* __restrict__ w1se,
    const float* __restrict__ w1vo, const float* __restrict__ w1ve,
    const float* __restrict__ stin_base) {
    __shared__ float ws[4096];
    int t = threadIdx.x;
    for (int i = t; i < 1024; i += 256) {
        ws[i] = w1so[i]; ws[1024+i] = w1se[i]; ws[2048+i] = w1vo[i]; ws[3072+i] = w1ve[i];
    }
    __syncthreads();
    int u = t & 31, wp = t >> 5;
    int n = blockIdx.x * 8 + wp;
    const float* s = stin_base + n * 256;
    float so = s[u], se = s[32+u];
    float vo0 = s[64+u*3], vo1 = s[64+u*3+1], vo2 = s[64+u*3+2];
    float ve0 = s[160+u*3], ve1 = s[160+u*3+1], ve2 = s[160+u*3+2];
    float aso=0, ase=0, avo0=0, avo1=0, avo2=0, ave0=0, ave1=0, ave2=0;
#pragma unroll
    for (int v = 0; v < 32; v++) {
        float a = __shfl_sync(WFULL, so, v), b = __shfl_sync(WFULL, se, v);
        float c0 = __shfl_sync(WFULL, vo0, v), c1 = __shfl_sync(WFULL, vo1, v), c2 = __shfl_sync(WFULL, vo2, v);
        float d0 = __shfl_sync(WFULL, ve0, v), d1 = __shfl_sync(WFULL, ve1, v), d2 = __shfl_sync(WFULL, ve2, v);
        float w0 = ws[v*32+u], w1 = ws[1024+v*32+u], w2 = ws[2048+v*32+u], w3 = ws[3072+v*32+u];
        aso += a*w0; ase += b*w1;
        avo0 += c0*w2; avo1 += c1*w2; avo2 += c2*w2;
        ave0 += d0*w3; ave1 += d1*w3; ave2 += d2*w3;
    }
    float* A = g_A + n * 256;
    A[u] = aso*IS32; A[32+u] = ase*IS32;
    A[64+u] = avo0*IS32; A[96+u] = avo1*IS32; A[128+u] = avo2*IS32;
    A[160+u] = ave0*IS32; A[192+u] = ave1*IS32; A[224+u] = ave2*IS32;
}

// dst-centric messages + fused node update (warp per node, table-interp w)
__global__ void __launch_bounds__(256) k_msg(
    const float* __restrict__ wsso, const float* __restrict__ wsse,
    const float* __restrict__ wsvo, const float* __restrict__ wsve,
    const float* __restrict__ w2so, const float* __restrict__ w2se,
    const float* __restrict__ w2vo, const float* __restrict__ w2ve,
    const float* __restrict__ stin_base, float* __restrict__ stout_base,
    const float* __restrict__ tab) {
    extern __shared__ float sm[];
    float* s_wsso = sm;
    float* s_wsse = sm + 1024;
    float* s_wsvo = sm + 4096;
    float* s_wsve = sm + 5120;
    float* s_w2so = sm + 6144;
    float* s_w2se = sm + 8192;
    float* s_w2vo = sm + 14336;
    float* s_w2ve = sm + 17408;
    int t = threadIdx.x;
    for (int i = t; i < 1024; i += 256) { s_wsso[i]=wsso[i]; s_wsvo[i]=wsvo[i]; s_wsve[i]=wsve[i]; }
    for (int i = t; i < 3072; i += 256) { s_wsse[i]=wsse[i]; s_w2vo[i]=w2vo[i]; s_w2ve[i]=w2ve[i]; }
    for (int i = t; i < 2048; i += 256) s_w2so[i]=w2so[i];
    for (int i = t; i < 6144; i += 256) s_w2se[i]=w2se[i];
    __syncthreads();
    int u = t & 31, wp = t >> 5;
    int n = blockIdx.x * 8 + wp;
    const float* stin = stin_base + n * 256;
    float* stout = stout_base + n * 256;

    float n0oa=0, n0ob=0, n0ea=0, n0eb=0;
    float p00=0,p01=0,p02=0,p10=0,p11=0,p12=0,p20=0,p21=0,p22=0;
    float q00=0,q01=0,q02=0,q10=0,q11=0,q12=0,q20=0,q21=0,q22=0;

    int beg = g_rowstart[n], end = g_rowstart[n+1];
    for (int idx = beg; idx < end; idx++) {
        int e = g_csr[idx];
        int src = g_csrc[idx];
        float4 y = g_y4[e];
        float2 rl = g_rl[e];
        int ri = (int)rl.x;
        float rf = rl.y;
        float y0 = y.x, y10 = y.y, y11 = y.z, y12 = y.w;
        const float* a = g_A + src * 256;
        float eso = a[u], ese = a[32+u];
        float evo0 = a[64+u], evo1 = a[96+u], evo2 = a[128+u];
        float eve0 = a[160+u], eve1 = a[192+u], eve2 = a[224+u];
        const float* ta = tab + (size_t)ri * 320 + u;
        float w0 = ta[0]   + rf*(ta[320] - ta[0]);
        float w1 = ta[32]  + rf*(ta[352] - ta[32]);
        float w2 = ta[64]  + rf*(ta[384] - ta[64]);
        float w3 = ta[96]  + rf*(ta[416] - ta[96]);
        float w4 = ta[128] + rf*(ta[448] - ta[128]);
        float w5 = ta[160] + rf*(ta[480] - ta[160]);
        float w6 = ta[192] + rf*(ta[512] - ta[192]);
        float w7 = ta[224] + rf*(ta[544] - ta[224]);
        float w8 = ta[256] + rf*(ta[576] - ta[256]);
        float w9 = ta[288] + rf*(ta[608] - ta[288]);
        float dve = (eve0*y10 + eve1*y11 + eve2*y12) * IV3;
        float dvo = (evo0*y10 + evo1*y11 + evo2*y12) * IV3;
        float cve0 = (eve1*y12 - eve2*y11) * IV2;
        float cve1 = (eve2*y10 - eve0*y12) * IV2;
        float cve2 = (eve0*y11 - eve1*y10) * IV2;
        float cvo0 = (evo1*y12 - evo2*y11) * IV2;
        float cvo1 = (evo2*y10 - evo0*y12) * IV2;
        float cvo2 = (evo0*y11 - evo1*y10) * IV2;
        n0oa += w0 * (eso * y0);  n0ob += w1 * dve;
        n0ea += w2 * (ese * y0);  n0eb += w3 * dvo;
        float sy = w4 * ese;
        p00 += sy*y10; p01 += sy*y11; p02 += sy*y12;
        float py = w5 * y0;
        p10 += py*evo0; p11 += py*evo1; p12 += py*evo2;
        p20 += w6*cve0; p21 += w6*cve1; p22 += w6*cve2;
        float qy = w7 * eso;
        q00 += qy*y10; q01 += qy*y11; q02 += qy*y12;
        q10 += w8*cvo0; q11 += w8*cvo1; q12 += w8*cvo2;
        float ry = w9 * y0;
        q20 += ry*eve0; q21 += ry*eve1; q22 += ry*eve2;
    }
    const float S0 = IV2 * 0.25f * CX8;
    const float S1 = IV3 * 0.25f * CX96;
    n0oa*=S0; n0ob*=S0; n0ea*=S0; n0eb*=S0;
    p00*=S1;p01*=S1;p02*=S1;p10*=S1;p11*=S1;p12*=S1;p20*=S1;p21*=S1;p22*=S1;
    q00*=S1;q01*=S1;q02*=S1;q10*=S1;q11*=S1;q12*=S1;q20*=S1;q21*=S1;q22*=S1;
    float so = stin[u]*CS32, se = stin[32+u]*CS32;
    float vo0 = stin[64+u*3]*CS32, vo1 = stin[64+u*3+1]*CS32, vo2 = stin[64+u*3+2]*CS32;
    float ve0 = stin[160+u*3]*CS32, ve1 = stin[160+u*3+1]*CS32, ve2 = stin[160+u*3+2]*CS32;

    float o0o=0, oe0=0, oe1=0, oe2=0;
    float t00=0,t01=0,t02=0,t10=0,t11=0,t12=0;
#pragma unroll 4
    for (int v = 0; v < 32; v++) {
        float sov = __shfl_sync(WFULL, so, v), sev = __shfl_sync(WFULL, se, v);
        float a0 = __shfl_sync(WFULL, n0oa, v), b0 = __shfl_sync(WFULL, n0ob, v);
        float a1 = __shfl_sync(WFULL, n0ea, v), b1 = __shfl_sync(WFULL, n0eb, v);
        float vo0v = __shfl_sync(WFULL, vo0, v), vo1v = __shfl_sync(WFULL, vo1, v), vo2v = __shfl_sync(WFULL, vo2, v);
        float ve0v = __shfl_sync(WFULL, ve0, v), ve1v = __shfl_sync(WFULL, ve1, v), ve2v = __shfl_sync(WFULL, ve2, v);
        float P00=__shfl_sync(WFULL,p00,v), P01=__shfl_sync(WFULL,p01,v), P02=__shfl_sync(WFULL,p02,v);
        float P10=__shfl_sync(WFULL,p10,v), P11=__shfl_sync(WFULL,p11,v), P12=__shfl_sync(WFULL,p12,v);
        float P20=__shfl_sync(WFULL,p20,v), P21=__shfl_sync(WFULL,p21,v), P22=__shfl_sync(WFULL,p22,v);
        float Q00=__shfl_sync(WFULL,q00,v), Q01=__shfl_sync(WFULL,q01,v), Q02=__shfl_sync(WFULL,q02,v);
        float Q10=__shfl_sync(WFULL,q10,v), Q11=__shfl_sync(WFULL,q11,v), Q12=__shfl_sync(WFULL,q12,v);
        float Q20=__shfl_sync(WFULL,q20,v), Q21=__shfl_sync(WFULL,q21,v), Q22=__shfl_sync(WFULL,q22,v);

        float wa = s_wsso[v*32+u];
        float m0 = s_w2so[v*32+u], m1 = s_w2so[(32+v)*32+u];
        o0o += sov*wa + a0*m0 + b0*m1;

        float wb0 = s_wsse[v*96+u], wb1 = s_wsse[v*96+32+u], wb2 = s_wsse[v*96+64+u];
        float n0 = s_w2se[v*96+u], n1 = s_w2se[v*96+32+u], n2 = s_w2se[v*96+64+u];
        float n3 = s_w2se[(32+v)*96+u], n4 = s_w2se[(32+v)*96+32+u], n5 = s_w2se[(32+v)*96+64+u];
        oe0 += sev*wb0 + a1*n0 + b1*n3;
        oe1 += sev*wb1 + a1*n1 + b1*n4;
        oe2 += sev*wb2 + a1*n2 + b1*n5;

        float wc = s_wsvo[v*32+u];
        float r0 = s_w2vo[v*32+u], r1 = s_w2vo[(32+v)*32+u], r2 = s_w2vo[(64+v)*32+u];
        t00 += vo0v*wc + P00*r0 + P10*r1 + P20*r2;
        t01 += vo1v*wc + P01*r0 + P11*r1 + P21*r2;
        t02 += vo2v*wc + P02*r0 + P12*r1 + P22*r2;

        float wd = s_wsve[v*32+u];
        float z0 = s_w2ve[v*32+u], z1 = s_w2ve[(32+v)*32+u], z2 = s_w2ve[(64+v)*32+u];
        t10 += ve0v*wd + Q00*z0 + Q10*z1 + Q20*z2;
        t11 += ve1v*wd + Q01*z0 + Q11*z1 + Q21*z2;
        t12 += ve2v*wd + Q02*z0 + Q12*z1 + Q22*z2;
    }
    float nso = tanhf(o0o);
    float nse = oe0 / (1.0f + __expf(-oe0));
    float g1 = 1.0f / (1.0f + __expf(-oe1));
    float g2 = 1.0f / (1.0f + __expf(-oe2));
    stout[u] = nso; stout[32+u] = nse;
    stout[64+u*3] = t00*g1; stout[64+u*3+1] = t01*g1; stout[64+u*3+2] = t02*g1;
    stout[160+u*3] = t10*g2; stout[160+u*3+1] = t11*g2; stout[160+u*3+2] = t12*g2;
}

// final head lin1
__global__ void __launch_bounds__(256) k_lin1f(
    const float* __restrict__ wse, const float* __restrict__ wvo) {
    __shared__ float ws[2048];
    int t = threadIdx.x;
    for (int i = t; i < 1024; i += 256) { ws[i] = wse[i]; ws[1024+i] = wvo[i]; }
    __syncthreads();
    int u = t & 31, wp = t >> 5;
    int n = blockIdx.x * 8 + wp;
    const float* s = g_state2 + n * 256;
    float se = s[32+u];
    float vo0 = s[64+u*3], vo1 = s[64+u*3+1], vo2 = s[64+u*3+2];
    float ase=0, av0=0, av1=0, av2=0;
#pragma unroll
    for (int v = 0; v < 32; v++) {
        float b = __shfl_sync(WFULL, se, v);
        float c0 = __shfl_sync(WFULL, vo0, v), c1 = __shfl_sync(WFULL, vo1, v), c2 = __shfl_sync(WFULL, vo2, v);
        float w0 = ws[v*32+u], w1 = ws[1024+v*32+u];
        ase += b*w0; av0 += c0*w1; av1 += c1*w1; av2 += c2*w1;
    }
    float* A = g_A + n * 256;
    A[u] = ase*IS32; A[32+u] = av0*IS32; A[64+u] = av1*IS32; A[96+u] = av2*IS32;
}

__global__ void __launch_bounds__(256) k_final(
    const int* __restrict__ batch,
    const float* __restrict__ fsc, const float* __restrict__ fl2,
    float* __restrict__ out) {
    int b = blockIdx.x, t = threadIdx.x, u = t & 31, wp = t >> 5;
    if (b < 32) g_deg[b*256 + t] = 0;
    else if (b < 64) g_cursor[(b-32)*256 + t] = 0;
    int n = b * 8 + wp;
    float na = 0, nb = 0;
    int beg = g_rowstart[n], end = g_rowstart[n+1];
    for (int idx = beg; idx < end; idx++) {
        int e = g_csr[idx];
        int src = g_csrc[idx];
        float4 y = g_y4[e];
        float2 rl = g_rl[e];
        int ri = (int)rl.x;
        float rf = rl.y;
        const float* a = g_A + src * 256;
        float ase = a[u], av0 = a[32+u], av1 = a[64+u], av2 = a[96+u];
        const float* ta = g_tabf + (size_t)ri * 64 + u;
        float w0 = ta[0]  + rf*(ta[64] - ta[0]);
        float w1 = ta[32] + rf*(ta[96] - ta[32]);
        float dvo = (av0*y.y + av1*y.z + av2*y.w) * IV3;
        na += w0 * (ase * y.x);
        nb += w1 * dvo;
    }
    const float S = IV2 * 0.25f;
    na *= S; nb *= S;
    float se = g_state2[n*256 + 32 + u];
    float val = CS32 * se * fsc[u] + CX8 * (na * fl2[u] + nb * fl2[32+u]);
#pragma unroll
    for (int off = 16; off > 0; off >>= 1)
        val += __shfl_xor_sync(WFULL, val, off);
    if (u == 0) atomicAdd(&out[batch[n]], val * OUTSC);
}

extern "C" void kernel_launch(void* const* d_in, const int* in_sizes, int n_in,
                              void* d_out, int out_size) {
    const float* x        = (const float*)d_in[0];
    const float* edge_vec = (const float*)d_in[1];
    const float* lin1_so  = (const float*)d_in[2];
    const float* lin1_se  = (const float*)d_in[3];
    const float* lin1_vo  = (const float*)d_in[4];
    const float* lin1_ve  = (const float*)d_in[5];
    const float* sc_so    = (const float*)d_in[6];
    const float* sc_se    = (const float*)d_in[7];
    const float* sc_vo    = (const float*)d_in[8];
    const float* sc_ve    = (const float*)d_in[9];
    const float* rad_w1   = (const float*)d_in[10];
    const float* rad_w2   = (const float*)d_in[11];
    const float* lin2_so  = (const float*)d_in[12];
    const float* lin2_se  = (const float*)d_in[13];
    const float* lin2_vo  = (const float*)d_in[14];
    const float* lin2_ve  = (const float*)d_in[15];
    const float* flin1_se = (const float*)d_in[16];
    const float* flin1_vo = (const float*)d_in[17];
    const float* fsc_se   = (const float*)d_in[18];
    const float* frad_w1  = (const float*)d_in[19];
    const float* frad_w2  = (const float*)d_in[20];
    const float* flin2    = (const float*)d_in[21];
    const int*   edge_src = (const int*)d_in[22];
    const int*   edge_dst = (const int*)d_in[23];
    const int*   batch    = (const int*)d_in[24];
    float* out = (float*)d_out;

    cudaFuncSetAttribute(k_msg, cudaFuncAttributeMaxDynamicSharedMemorySize, 81920);

    float* st2; cudaGetSymbolAddress((void**)&st2, g_state2);
    float* st1; cudaGetSymbolAddress((void**)&st1, g_state);
    float* tab; cudaGetSymbolAddress((void**)&tab, g_tab);

    k_setup<<<2560, 256>>>(x, edge_vec, edge_dst,
                           lin1_so, lin1_se, lin1_vo, lin1_ve,
                           rad_w1, rad_w2, frad_w1, frad_w2);                    // 1
    k_scan<<<1, 1024>>>(out);                                                    // 2
    k_scatter<<<512, 256>>>(edge_dst, edge_src);                                 // 3
    k_msg<<<1024, 256, 81920>>>(sc_so, sc_se, sc_vo, sc_ve,
                                lin2_so, lin2_se, lin2_vo, lin2_ve,
                                x, st2, tab);                                    // 4 (profiled)
    k_lin1<<<1024, 256>>>(lin1_so + 1024, lin1_se + 1024,
                          lin1_vo + 1024, lin1_ve + 1024, st2);                  // 5
    k_msg<<<1024, 256, 81920>>>(sc_so + 1024, sc_se + 3072, sc_vo + 1024, sc_ve + 1024,
                                lin2_so + 2048, lin2_se + 6144,
                                lin2_vo + 3072, lin2_ve + 3072,
                                st2, st1, tab + (size_t)NK*320);                 // 6
    k_lin1<<<1024, 256>>>(lin1_so + 2048, lin1_se + 2048,
                          lin1_vo + 2048, lin1_ve + 2048, st1);                  // 7
    k_msg<<<1024, 256, 81920>>>(sc_so + 2048, sc_se + 6144, sc_vo + 2048, sc_ve + 2048,
                                lin2_so + 4096, lin2_se + 12288,
                                lin2_vo + 6144, lin2_ve + 6144,
                                st1, st2, tab + (size_t)2*NK*320);               // 8
    k_lin1f<<<1024, 256>>>(flin1_se, flin1_vo);                                  // 9
    k_final<<<1024, 256>>>(batch, fsc_se, flin2, out);                           // 10
}

// round 14
// speedup vs baseline: 3.3255x; 1.2880x over previous
#include <cuda_runtime.h>
#include <math.h>

#define EN 131072
#define NN 8192
#define NK 8192
#define WFULL 0xffffffffu

__device__ float4 g_y4[EN];
__device__ float2 g_rl[EN];
__device__ float g_state[NN * 256];
__device__ float g_state2[NN * 256];
__device__ float g_A[NN * 256];
__device__ float g_tab[3 * NK * 320];
__device__ float g_tabf[NK * 64];
__device__ int   g_deg[NN];
__device__ int   g_cursor[NN];
__device__ int   g_rowstart[NN + 1];
__device__ int   g_csr[EN];
__device__ int   g_csrc[EN];

#define IS32 0.17677669529663687f
#define IS10 0.31622776601683794f
#define IV2  0.7071067811865476f
#define IV3  0.5773502691896258f
#define CSC  0.3826834323650898f
#define CXC  0.9238795325112867f
#define CS32 (CSC * IS32)
#define CX8  (CXC * 0.125f)
#define CX96 (CXC * 0.10206207261596575f)
#define EMBSC 2.8234622306428f
#define OUTSC 0.044194173824159216f
#define RDELTA (8.0f / 8191.0f)
#define RINV   (8191.0f / 8.0f)

// table builder: 32 knots per block, ncol outputs per knot
__device__ __forceinline__ void dev_table(
    const float* __restrict__ rw1, const float* __restrict__ rw2,
    float* __restrict__ tab, int ncol, int knot0, float* sbuf) {
    float* h  = sbuf;          // 3200
    float* em = sbuf + 3200;   // 320
    int t = threadIdx.x;
    for (int i = t; i < 320; i += 256) {
        int k = i / 10, j = i - k * 10;
        float r = (float)(knot0 + k) * RDELTA;
        float d = (r - (float)j * (4.0f/9.0f)) * 2.25f;
        em[i] = expf(-d*d) * EMBSC;
    }
    __syncthreads();
    for (int i = t; i < 3200; i += 256) {
        int k = i / 100, j = i - k * 100;
        float s = 0.0f;
#pragma unroll
        for (int m = 0; m < 10; m++) s += em[k*10+m] * rw1[m*100+j];
        s *= IS10;
        h[i] = s / (1.0f + __expf(-s));
    }
    __syncthreads();
    int total = 32 * ncol;
    for (int i = t; i < total; i += 256) {
        int k = i / ncol, col = i - k * ncol;
        float acc = 0.0f;
#pragma unroll 4
        for (int m = 0; m < 100; m++) acc += h[k*100+m] * rw2[m*ncol+col];
        tab[(size_t)(knot0 + k) * ncol + col] = acc * 0.1f;
    }
}

// ===== k_setup: geom+hist (b<512) | lin1 layer0 (512..1535) | tables (1536..2559)
__global__ void __launch_bounds__(256) k_setup(
    const float* __restrict__ x, const float* __restrict__ ev,
    const int* __restrict__ dst,
    const float* __restrict__ w1so, const float* __restrict__ w1se,
    const float* __restrict__ w1vo, const float* __restrict__ w1ve,
    const float* __restrict__ rw1, const float* __restrict__ rw2,
    const float* __restrict__ frw1, const float* __restrict__ frw2) {
    __shared__ float sbuf[4096];
    int b = blockIdx.x, t = threadIdx.x;
    if (b < 512) {
        int e = b * 256 + t;
        float vx = ev[e*3], vy = ev[e*3+1], vz = ev[e*3+2];
        float r = sqrtf(vx*vx + vy*vy + vz*vz);
        float inv = 1.0f / (r + 1e-12f);
        float uu = 0.5f * r - 2.0f;
        float cut;
        if (uu > 0.0f) cut = 0.0f;
        else if (uu < -1.0f) cut = 1.0f;
        else cut = 0.5f * (1.0f - cosf(3.14159265358979323846f * uu));
        const float SQ3 = 1.7320508075688772f;
        float s = SQ3 * inv * cut;
        g_y4[e] = make_float4(cut, s*vx, s*vy, s*vz);
        float xq = r * RINV;
        int ri = (int)xq;
        if (ri > NK - 2) ri = NK - 2;
        float rf = xq - (float)ri;
        if (rf > 1.0f) rf = 1.0f;
        g_rl[e] = make_float2((float)ri, rf);
        atomicAdd(&g_deg[dst[e]], 1);
        return;
    }
    if (b >= 1536) {
        int tb = b - 1536;
        if (tb < 768) {
            int layer = tb >> 8, kg = tb & 255;
            dev_table(rw1 + layer*1000, rw2 + layer*32000,
                      g_tab + (size_t)layer*NK*320, 320, kg*32, sbuf);
        } else {
            int kg = tb - 768;
            dev_table(frw1, frw2, g_tabf, 64, kg*32, sbuf);
        }
        return;
    }
    // lin1 layer 0
    float* ws = sbuf;
    for (int i = t; i < 1024; i += 256) {
        ws[i] = w1so[i]; ws[1024+i] = w1se[i]; ws[2048+i] = w1vo[i]; ws[3072+i] = w1ve[i];
    }
    __syncthreads();
    int u = t & 31, wp = t >> 5;
    int n = (b - 512) * 8 + wp;
    const float* s = x + n * 256;
    float so = s[u], se = s[32+u];
    float vo0 = s[64+u*3], vo1 = s[64+u*3+1], vo2 = s[64+u*3+2];
    float ve0 = s[160+u*3], ve1 = s[160+u*3+1], ve2 = s[160+u*3+2];
    float aso=0, ase=0, avo0=0, avo1=0, avo2=0, ave0=0, ave1=0, ave2=0;
#pragma unroll
    for (int v = 0; v < 32; v++) {
        float a = __shfl_sync(WFULL, so, v), bb = __shfl_sync(WFULL, se, v);
        float c0 = __shfl_sync(WFULL, vo0, v), c1 = __shfl_sync(WFULL, vo1, v), c2 = __shfl_sync(WFULL, vo2, v);
        float d0 = __shfl_sync(WFULL, ve0, v), d1 = __shfl_sync(WFULL, ve1, v), d2 = __shfl_sync(WFULL, ve2, v);
        float w0 = ws[v*32+u], w1 = ws[1024+v*32+u], w2 = ws[2048+v*32+u], w3 = ws[3072+v*32+u];
        aso += a*w0; ase += bb*w1;
        avo0 += c0*w2; avo1 += c1*w2; avo2 += c2*w2;
        ave0 += d0*w3; ave1 += d1*w3; ave2 += d2*w3;
    }
    float* A = g_A + n * 256;
    A[u] = aso*IS32; A[32+u] = ase*IS32;
    A[64+u] = avo0*IS32; A[96+u] = avo1*IS32; A[128+u] = avo2*IS32;
    A[160+u] = ave0*IS32; A[192+u] = ave1*IS32; A[224+u] = ave2*IS32;
}

__global__ void k_scan(float* __restrict__ out) {
    __shared__ int part[1024];
    int t = threadIdx.x;
    if (t < 16) out[t] = 0.0f;
    int loc[8]; int run = 0;
#pragma unroll
    for (int i = 0; i < 8; i++) { loc[i] = run; run += g_deg[t*8+i]; }
    part[t] = run;
    __syncthreads();
    for (int off = 1; off < 1024; off <<= 1) {
        int xv = (t >= off) ? part[t-off] : 0;
        __syncthreads();
        part[t] += xv;
        __syncthreads();
    }
    int base = (t > 0) ? part[t-1] : 0;
#pragma unroll
    for (int i = 0; i < 8; i++) g_rowstart[t*8+i] = base + loc[i];
    if (t == 1023) g_rowstart[NN] = EN;
}

__global__ void k_scatter(const int* __restrict__ dst, const int* __restrict__ src) {
    int e = blockIdx.x * blockDim.x + threadIdx.x;
    if (e >= EN) return;
    int d = dst[e];
    int pos = atomicAdd(&g_cursor[d], 1);
    int slot = g_rowstart[d] + pos;
    g_csr[slot] = e;
    g_csrc[slot] = src[e];
}

// node linear-1 (layers 1,2)
__global__ void __launch_bounds__(256) k_lin1(
    const float* __restrict__ w1so, const float* __restrict__ w1se,
    const float* __restrict__ w1vo, const float* __restrict__ w1ve,
    const float* __restrict__ stin_base) {
    __shared__ float ws[4096];
    int t = threadIdx.x;
    for (int i = t; i < 1024; i += 256) {
        ws[i] = w1so[i]; ws[1024+i] = w1se[i]; ws[2048+i] = w1vo[i]; ws[3072+i] = w1ve[i];
    }
    __syncthreads();
    int u = t & 31, wp = t >> 5;
    int n = blockIdx.x * 8 + wp;
    const float* s = stin_base + n * 256;
    float so = s[u], se = s[32+u];
    float vo0 = s[64+u*3], vo1 = s[64+u*3+1], vo2 = s[64+u*3+2];
    float ve0 = s[160+u*3], ve1 = s[160+u*3+1], ve2 = s[160+u*3+2];
    float aso=0, ase=0, avo0=0, avo1=0, avo2=0, ave0=0, ave1=0, ave2=0;
#pragma unroll
    for (int v = 0; v < 32; v++) {
        float a = __shfl_sync(WFULL, so, v), b = __shfl_sync(WFULL, se, v);
        float c0 = __shfl_sync(WFULL, vo0, v), c1 = __shfl_sync(WFULL, vo1, v), c2 = __shfl_sync(WFULL, vo2, v);
        float d0 = __shfl_sync(WFULL, ve0, v), d1 = __shfl_sync(WFULL, ve1, v), d2 = __shfl_sync(WFULL, ve2, v);
        float w0 = ws[v*32+u], w1 = ws[1024+v*32+u], w2 = ws[2048+v*32+u], w3 = ws[3072+v*32+u];
        aso += a*w0; ase += b*w1;
        avo0 += c0*w2; avo1 += c1*w2; avo2 += c2*w2;
        ave0 += d0*w3; ave1 += d1*w3; ave2 += d2*w3;
    }
    float* A = g_A + n * 256;
    A[u] = aso*IS32; A[32+u] = ase*IS32;
    A[64+u] = avo0*IS32; A[96+u] = avo1*IS32; A[128+u] = avo2*IS32;
    A[160+u] = ave0*IS32; A[192+u] = ave1*IS32; A[224+u] = ave2*IS32;
}

// dst-centric messages + fused node update
// 512 threads = 16 warps = 16 nodes/block; edge loop software-pipelined.
__global__ void __launch_bounds__(512) k_msg(
    const float* __restrict__ wsso, const float* __restrict__ wsse,
    const float* __restrict__ wsvo, const float* __restrict__ wsve,
    const float* __restrict__ w2so, const float* __restrict__ w2se,
    const float* __restrict__ w2vo, const float* __restrict__ w2ve,
    const float* __restrict__ stin_base, float* __restrict__ stout_base,
    const float* __restrict__ tab) {
    extern __shared__ float sm[];
    float* s_wsso = sm;
    float* s_wsse = sm + 1024;
    float* s_wsvo = sm + 4096;
    float* s_wsve = sm + 5120;
    float* s_w2so = sm + 6144;
    float* s_w2se = sm + 8192;
    float* s_w2vo = sm + 14336;
    float* s_w2ve = sm + 17408;
    int t = threadIdx.x;
    for (int i = t; i < 1024; i += 512) { s_wsso[i]=wsso[i]; s_wsvo[i]=wsvo[i]; s_wsve[i]=wsve[i]; }
    for (int i = t; i < 3072; i += 512) { s_wsse[i]=wsse[i]; s_w2vo[i]=w2vo[i]; s_w2ve[i]=w2ve[i]; }
    for (int i = t; i < 2048; i += 512) s_w2so[i]=w2so[i];
    for (int i = t; i < 6144; i += 512) s_w2se[i]=w2se[i];
    __syncthreads();
    int u = t & 31, wp = t >> 5;
    int n = blockIdx.x * 16 + wp;
    const float* stin = stin_base + n * 256;
    float* stout = stout_base + n * 256;

    float n0oa=0, n0ob=0, n0ea=0, n0eb=0;
    float p00=0,p01=0,p02=0,p10=0,p11=0,p12=0,p20=0,p21=0,p22=0;
    float q00=0,q01=0,q02=0,q10=0,q11=0,q12=0,q20=0,q21=0,q22=0;

    int beg = g_rowstart[n], end = g_rowstart[n+1];
    int e = 0, src = 0;
    float4 y = make_float4(0,0,0,0);
    float2 rl = make_float2(0,0);
    if (beg < end) {
        e = g_csr[beg]; src = g_csrc[beg];
        y = g_y4[e]; rl = g_rl[e];
    }
    for (int idx = beg; idx < end; idx++) {
        // current edge state in registers; prefetch next
        int ce = e, csrc = src;
        float4 cy = y; float2 crl = rl;
        int nx = idx + 1;
        if (nx < end) {
            int e2 = g_csr[nx], s2 = g_csrc[nx];
            y = g_y4[e2]; rl = g_rl[e2];
            e = e2; src = s2;
        }
        int ri = (int)crl.x;
        float rf = crl.y;
        float y0 = cy.x, y10 = cy.y, y11 = cy.z, y12 = cy.w;
        const float* a = g_A + csrc * 256;
        float eso = a[u], ese = a[32+u];
        float evo0 = a[64+u], evo1 = a[96+u], evo2 = a[128+u];
        float eve0 = a[160+u], eve1 = a[192+u], eve2 = a[224+u];
        const float* ta = tab + (size_t)ri * 320 + u;
        float w0 = ta[0]   + rf*(ta[320] - ta[0]);
        float w1 = ta[32]  + rf*(ta[352] - ta[32]);
        float w2 = ta[64]  + rf*(ta[384] - ta[64]);
        float w3 = ta[96]  + rf*(ta[416] - ta[96]);
        float w4 = ta[128] + rf*(ta[448] - ta[128]);
        float w5 = ta[160] + rf*(ta[480] - ta[160]);
        float w6 = ta[192] + rf*(ta[512] - ta[192]);
        float w7 = ta[224] + rf*(ta[544] - ta[224]);
        float w8 = ta[256] + rf*(ta[576] - ta[256]);
        float w9 = ta[288] + rf*(ta[608] - ta[288]);
        float dve = (eve0*y10 + eve1*y11 + eve2*y12) * IV3;
        float dvo = (evo0*y10 + evo1*y11 + evo2*y12) * IV3;
        float cve0 = (eve1*y12 - eve2*y11) * IV2;
        float cve1 = (eve2*y10 - eve0*y12) * IV2;
        float cve2 = (eve0*y11 - eve1*y10) * IV2;
        float cvo0 = (evo1*y12 - evo2*y11) * IV2;
        float cvo1 = (evo2*y10 - evo0*y12) * IV2;
        float cvo2 = (evo0*y11 - evo1*y10) * IV2;
        n0oa += w0 * (eso * y0);  n0ob += w1 * dve;
        n0ea += w2 * (ese * y0);  n0eb += w3 * dvo;
        float sy = w4 * ese;
        p00 += sy*y10; p01 += sy*y11; p02 += sy*y12;
        float py = w5 * y0;
        p10 += py*evo0; p11 += py*evo1; p12 += py*evo2;
        p20 += w6*cve0; p21 += w6*cve1; p22 += w6*cve2;
        float qy = w7 * eso;
        q00 += qy*y10; q01 += qy*y11; q02 += qy*y12;
        q10 += w8*cvo0; q11 += w8*cvo1; q12 += w8*cvo2;
        float ry = w9 * y0;
        q20 += ry*eve0; q21 += ry*eve1; q22 += ry*eve2;
    }
    const float S0 = IV2 * 0.25f * CX8;
    const float S1 = IV3 * 0.25f * CX96;
    n0oa*=S0; n0ob*=S0; n0ea*=S0; n0eb*=S0;
    p00*=S1;p01*=S1;p02*=S1;p10*=S1;p11*=S1;p12*=S1;p20*=S1;p21*=S1;p22*=S1;
    q00*=S1;q01*=S1;q02*=S1;q10*=S1;q11*=S1;q12*=S1;q20*=S1;q21*=S1;q22*=S1;
    float so = stin[u]*CS32, se = stin[32+u]*CS32;
    float vo0 = stin[64+u*3]*CS32, vo1 = stin[64+u*3+1]*CS32, vo2 = stin[64+u*3+2]*CS32;
    float ve0 = stin[160+u*3]*CS32, ve1 = stin[160+u*3+1]*CS32, ve2 = stin[160+u*3+2]*CS32;

    float o0o=0, oe0=0, oe1=0, oe2=0;
    float t00=0,t01=0,t02=0,t10=0,t11=0,t12=0;
#pragma unroll 4
    for (int v = 0; v < 32; v++) {
        float sov = __shfl_sync(WFULL, so, v), sev = __shfl_sync(WFULL, se, v);
        float a0 = __shfl_sync(WFULL, n0oa, v), b0 = __shfl_sync(WFULL, n0ob, v);
        float a1 = __shfl_sync(WFULL, n0ea, v), b1 = __shfl_sync(WFULL, n0eb, v);
        float vo0v = __shfl_sync(WFULL, vo0, v), vo1v = __shfl_sync(WFULL, vo1, v), vo2v = __shfl_sync(WFULL, vo2, v);
        float ve0v = __shfl_sync(WFULL, ve0, v), ve1v = __shfl_sync(WFULL, ve1, v), ve2v = __shfl_sync(WFULL, ve2, v);
        float P00=__shfl_sync(WFULL,p00,v), P01=__shfl_sync(WFULL,p01,v), P02=__shfl_sync(WFULL,p02,v);
        float P10=__shfl_sync(WFULL,p10,v), P11=__shfl_sync(WFULL,p11,v), P12=__shfl_sync(WFULL,p12,v);
        float P20=__shfl_sync(WFULL,p20,v), P21=__shfl_sync(WFULL,p21,v), P22=__shfl_sync(WFULL,p22,v);
        float Q00=__shfl_sync(WFULL,q00,v), Q01=__shfl_sync(WFULL,q01,v), Q02=__shfl_sync(WFULL,q02,v);
        float Q10=__shfl_sync(WFULL,q10,v), Q11=__shfl_sync(WFULL,q11,v), Q12=__shfl_sync(WFULL,q12,v);
        float Q20=__shfl_sync(WFULL,q20,v), Q21=__shfl_sync(WFULL,q21,v), Q22=__shfl_sync(WFULL,q22,v);

        float wa = s_wsso[v*32+u];
        float m0 = s_w2so[v*32+u], m1 = s_w2so[(32+v)*32+u];
        o0o += sov*wa + a0*m0 + b0*m1;

        float wb0 = s_wsse[v*96+u], wb1 = s_wsse[v*96+32+u], wb2 = s_wsse[v*96+64+u];
        float n0 = s_w2se[v*96+u], n1 = s_w2se[v*96+32+u], n2 = s_w2se[v*96+64+u];
        float n3 = s_w2se[(32+v)*96+u], n4 = s_w2se[(32+v)*96+32+u], n5 = s_w2se[(32+v)*96+64+u];
        oe0 += sev*wb0 + a1*n0 + b1*n3;
        oe1 += sev*wb1 + a1*n1 + b1*n4;
        oe2 += sev*wb2 + a1*n2 + b1*n5;

        float wc = s_wsvo[v*32+u];
        float r0 = s_w2vo[v*32+u], r1 = s_w2vo[(32+v)*32+u], r2 = s_w2vo[(64+v)*32+u];
        t00 += vo0v*wc + P00*r0 + P10*r1 + P20*r2;
        t01 += vo1v*wc + P01*r0 + P11*r1 + P21*r2;
        t02 += vo2v*wc + P02*r0 + P12*r1 + P22*r2;

        float wd = s_wsve[v*32+u];
        float z0 = s_w2ve[v*32+u], z1 = s_w2ve[(32+v)*32+u], z2 = s_w2ve[(64+v)*32+u];
        t10 += ve0v*wd + Q00*z0 + Q10*z1 + Q20*z2;
        t11 += ve1v*wd + Q01*z0 + Q11*z1 + Q21*z2;
        t12 += ve2v*wd + Q02*z0 + Q12*z1 + Q22*z2;
    }
    float nso = tanhf(o0o);
    float nse = oe0 / (1.0f + __expf(-oe0));
    float g1 = 1.0f / (1.0f + __expf(-oe1));
    float g2 = 1.0f / (1.0f + __expf(-oe2));
    stout[u] = nso; stout[32+u] = nse;
    stout[64+u*3] = t00*g1; stout[64+u*3+1] = t01*g1; stout[64+u*3+2] = t02*g1;
    stout[160+u*3] = t10*g2; stout[160+u*3+1] = t11*g2; stout[160+u*3+2] = t12*g2;
}

// final head lin1
__global__ void __launch_bounds__(256) k_lin1f(
    const float* __restrict__ wse, const float* __restrict__ wvo) {
    __shared__ float ws[2048];
    int t = threadIdx.x;
    for (int i = t; i < 1024; i += 256) { ws[i] = wse[i]; ws[1024+i] = wvo[i]; }
    __syncthreads();
    int u = t & 31, wp = t >> 5;
    int n = blockIdx.x * 8 + wp;
    const float* s = g_state2 + n * 256;
    float se = s[32+u];
    float vo0 = s[64+u*3], vo1 = s[64+u*3+1], vo2 = s[64+u*3+2];
    float ase=0, av0=0, av1=0, av2=0;
#pragma unroll
    for (int v = 0; v < 32; v++) {
        float b = __shfl_sync(WFULL, se, v);
        float c0 = __shfl_sync(WFULL, vo0, v), c1 = __shfl_sync(WFULL, vo1, v), c2 = __shfl_sync(WFULL, vo2, v);
        float w0 = ws[v*32+u], w1 = ws[1024+v*32+u];
        ase += b*w0; av0 += c0*w1; av1 += c1*w1; av2 += c2*w1;
    }
    float* A = g_A + n * 256;
    A[u] = ase*IS32; A[32+u] = av0*IS32; A[64+u] = av1*IS32; A[96+u] = av2*IS32;
}

__global__ void __launch_bounds__(256) k_final(
    const int* __restrict__ batch,
    const float* __restrict__ fsc, const float* __restrict__ fl2,
    float* __restrict__ out) {
    int b = blockIdx.x, t = threadIdx.x, u = t & 31, wp = t >> 5;
    if (b < 32) g_deg[b*256 + t] = 0;
    else if (b < 64) g_cursor[(b-32)*256 + t] = 0;
    int n = b * 8 + wp;
    float na = 0, nb = 0;
    int beg = g_rowstart[n], end = g_rowstart[n+1];
    for (int idx = beg; idx < end; idx++) {
        int e = g_csr[idx];
        int src = g_csrc[idx];
        float4 y = g_y4[e];
        float2 rl = g_rl[e];
        int ri = (int)rl.x;
        float rf = rl.y;
        const float* a = g_A + src * 256;
        float ase = a[u], av0 = a[32+u], av1 = a[64+u], av2 = a[96+u];
        const float* ta = g_tabf + (size_t)ri * 64 + u;
        float w0 = ta[0]  + rf*(ta[64] - ta[0]);
        float w1 = ta[32] + rf*(ta[96] - ta[32]);
        float dvo = (av0*y.y + av1*y.z + av2*y.w) * IV3;
        na += w0 * (ase * y.x);
        nb += w1 * dvo;
    }
    const float S = IV2 * 0.25f;
    na *= S; nb *= S;
    float se = g_state2[n*256 + 32 + u];
    float val = CS32 * se * fsc[u] + CX8 * (na * fl2[u] + nb * fl2[32+u]);
#pragma unroll
    for (int off = 16; off > 0; off >>= 1)
        val += __shfl_xor_sync(WFULL, val, off);
    if (u == 0) atomicAdd(&out[batch[n]], val * OUTSC);
}

extern "C" void kernel_launch(void* const* d_in, const int* in_sizes, int n_in,
                              void* d_out, int out_size) {
    const float* x        = (const float*)d_in[0];
    const float* edge_vec = (const float*)d_in[1];
    const float* lin1_so  = (const float*)d_in[2];
    const float* lin1_se  = (const float*)d_in[3];
    const float* lin1_vo  = (const float*)d_in[4];
    const float* lin1_ve  = (const float*)d_in[5];
    const float* sc_so    = (const float*)d_in[6];
    const float* sc_se    = (const float*)d_in[7];
    const float* sc_vo    = (const float*)d_in[8];
    const float* sc_ve    = (const float*)d_in[9];
    const float* rad_w1   = (const float*)d_in[10];
    const float* rad_w2   = (const float*)d_in[11];
    const float* lin2_so  = (const float*)d_in[12];
    const float* lin2_se  = (const float*)d_in[13];
    const float* lin2_vo  = (const float*)d_in[14];
    const float* lin2_ve  = (const float*)d_in[15];
    const float* flin1_se = (const float*)d_in[16];
    const float* flin1_vo = (const float*)d_in[17];
    const float* fsc_se   = (const float*)d_in[18];
    const float* frad_w1  = (const float*)d_in[19];
    const float* frad_w2  = (const float*)d_in[20];
    const float* flin2    = (const float*)d_in[21];
    const int*   edge_src = (const int*)d_in[22];
    const int*   edge_dst = (const int*)d_in[23];
    const int*   batch    = (const int*)d_in[24];
    float* out = (float*)d_out;

    cudaFuncSetAttribute(k_msg, cudaFuncAttributeMaxDynamicSharedMemorySize, 81920);

    float* st2; cudaGetSymbolAddress((void**)&st2, g_state2);
    float* st1; cudaGetSymbolAddress((void**)&st1, g_state);
    float* tab; cudaGetSymbolAddress((void**)&tab, g_tab);

    k_setup<<<2560, 256>>>(x, edge_vec, edge_dst,
                           lin1_so, lin1_se, lin1_vo, lin1_ve,
                           rad_w1, rad_w2, frad_w1, frad_w2);                    // 1
    k_scan<<<1, 1024>>>(out);                                                    // 2
    k_scatter<<<512, 256>>>(edge_dst, edge_src);                                 // 3
    k_msg<<<512, 512, 81920>>>(sc_so, sc_se, sc_vo, sc_ve,
                               lin2_so, lin2_se, lin2_vo, lin2_ve,
                               x, st2, tab);                                     // 4 (profiled)
    k_lin1<<<1024, 256>>>(lin1_so + 1024, lin1_se + 1024,
                          lin1_vo + 1024, lin1_ve + 1024, st2);                  // 5
    k_msg<<<512, 512, 81920>>>(sc_so + 1024, sc_se + 3072, sc_vo + 1024, sc_ve + 1024,
                               lin2_so + 2048, lin2_se + 6144,
                               lin2_vo + 3072, lin2_ve + 3072,
                               st2, st1, tab + (size_t)NK*320);                  // 6
    k_lin1<<<1024, 256>>>(lin1_so + 2048, lin1_se + 2048,
                          lin1_vo + 2048, lin1_ve + 2048, st1);                  // 7
    k_msg<<<512, 512, 81920>>>(sc_so + 2048, sc_se + 6144, sc_vo + 2048, sc_ve + 2048,
                               lin2_so + 4096, lin2_se + 12288,
                               lin2_vo + 6144, lin2_ve + 6144,
                               st1, st2, tab + (size_t)2*NK*320);                // 8
    k_lin1f<<<1024, 256>>>(flin1_se, flin1_vo);                                  // 9
    k_final<<<1024, 256>>>(batch, fsc_se, flin2, out);                           // 10
}